// round 2
// baseline (speedup 1.0000x reference)
#include <cuda_runtime.h>

// ---------------- problem dims ----------------
constexpr int B = 2, D1 = 8, D2 = 16, D3 = 32, D4 = 32, F = 8, H = 16, H2 = 32;
constexpr int NV = B * D1 * D2 * D3 * D4;  // 262144 voxels
constexpr float LRELU = 0.01f;

typedef unsigned long long ull;

// ---------------- static scratch (no allocation allowed) ----------------
__device__ float g_bufA[NV * H];     // embed out / conv3 out
__device__ float g_bufB[NV * H];     // conv1 out
__device__ float g_bufC[NV * H2];    // conv2 out
__device__ float g_W1t[625 * H * H];
__device__ float g_W2t[625 * H * H2];
__device__ float g_W3t[625 * H2 * H];
__device__ double g_sum[3 * 32];
__device__ double g_ssq[3 * 32];

// ---------------- f32x2 helpers (FFMA2 is PTX-only on sm_103a) ----------------
__device__ __forceinline__ ull ffma2(ull a, ull b, ull c) {
    ull d;
    asm("fma.rn.f32x2 %0, %1, %2, %3;" : "=l"(d) : "l"(a), "l"(b), "l"(c));
    return d;
}
__device__ __forceinline__ ull pack2(float x) {
    ull r;
    asm("mov.b64 %0, {%1, %1};" : "=l"(r) : "f"(x));
    return r;
}

union U2F4 { ull u[2]; float4 f; };

// ---------------- small kernels ----------------
__global__ void zero_stats_kernel(double* s, double* q) {
    int i = threadIdx.x;
    if (i < 96) { s[i] = 0.0; q[i] = 0.0; }
}

// W[cout][cin][625] -> Wt[tap][cin][cout]
__global__ void reorder_w_kernel(const float* __restrict__ src, float* __restrict__ dst,
                                 int CIN, int COUT) {
    int n = 625 * CIN * COUT;
    int i = blockIdx.x * blockDim.x + threadIdx.x;
    if (i >= n) return;
    int co  = i % COUT;
    int ci  = (i / COUT) % CIN;
    int tap = i / (COUT * CIN);
    dst[i] = src[(co * CIN + ci) * 625 + tap];
}

// h[v][h16] = x[v][f8] @ w_emb[f][h] + b_emb
__global__ void embed_kernel(const float* __restrict__ x, const float* __restrict__ we,
                             const float* __restrict__ be, float* __restrict__ out) {
    __shared__ float sw[F * H];
    __shared__ float sb[H];
    if (threadIdx.x < F * H) sw[threadIdx.x] = we[threadIdx.x];
    if (threadIdx.x < H) sb[threadIdx.x] = be[threadIdx.x];
    __syncthreads();
    int v = blockIdx.x * blockDim.x + threadIdx.x;
    if (v >= NV) return;
    float xf[F];
    const float4* xp = (const float4*)(x + v * F);
    float4 x0 = xp[0], x1 = xp[1];
    xf[0]=x0.x; xf[1]=x0.y; xf[2]=x0.z; xf[3]=x0.w;
    xf[4]=x1.x; xf[5]=x1.y; xf[6]=x1.z; xf[7]=x1.w;
    float o[H];
#pragma unroll
    for (int h = 0; h < H; h++) {
        float a = sb[h];
#pragma unroll
        for (int f = 0; f < F; f++) a += xf[f] * sw[f * H + h];
        o[h] = a;
    }
    float4* op = (float4*)(out + v * H);
#pragma unroll
    for (int k = 0; k < 4; k++) op[k] = make_float4(o[4*k], o[4*k+1], o[4*k+2], o[4*k+3]);
}

// ---------------- 4D conv (FFMA2, register-resident couts) ----------------
// Block covers (b, d1, d2) x BROWS d3-rows x all 32 d4.
// Warp: 32 lanes = d4; rg = row-quad (4 d3 rows), ch = cout-half.
// Each thread accumulates 4 rows x COUT_T(16) couts as 32 f32x2 pairs.
// s_in layout [c4][srow][36 d4pad] (float4) -> per-lane LDS.128 conflict-free.
// Weight LDS are warp-uniform broadcasts.
template <int CIN, int COUT, int BROWS, int NW>
__global__ void __launch_bounds__(NW * 32)
conv4d_kernel(const float* __restrict__ in, const float* __restrict__ wt,
              const float* __restrict__ bias, float* __restrict__ out) {
    constexpr int C4    = CIN / 4;
    constexpr int SROWS = BROWS + 4;
    constexpr int NRG   = BROWS / 4;
    constexpr int NCH   = NW / NRG;
    constexpr int COUT_T = COUT / NCH;            // 16
    constexpr int NTHR  = NW * 32;
    constexpr int SIN4  = C4 * SROWS * 36;        // float4 count
    constexpr int SWF   = 25 * CIN * COUT;        // floats per (dt,dz) slab
    constexpr int DB3   = D3 / BROWS;

    extern __shared__ float smem[];
    float4* s_in = (float4*)smem;                 // [c4][srow][36]
    float*  s_w  = smem + SIN4 * 4;               // [tap25][ci][cout]

    int bi   = blockIdx.x;
    int d3b  = (bi % DB3) * BROWS;
    int rest = bi / DB3;
    int d2 = rest & 15, d1 = (rest >> 4) & 7, b = rest >> 7;

    int tid  = threadIdx.x;
    int wid  = tid >> 5, lane = tid & 31;
    int rg   = wid % NRG, ch = wid / NRG;
    int cb   = ch * COUT_T;
    int d4   = lane;
    int rbase = rg * 4;

    ull acc[4][COUT_T / 2];
    {
        const ull* bp = (const ull*)(bias + cb);
#pragma unroll
        for (int j = 0; j < 4; j++)
#pragma unroll
            for (int p = 0; p < COUT_T / 2; p++) acc[j][p] = bp[p];
    }

    const float4* in4 = (const float4*)in;
    const float4* wt4 = (const float4*)wt;

    for (int dt = 0; dt < 5; dt++) {
        int d1s = d1 + dt - 2;
        for (int dz = 0; dz < 5; dz++) {
            int d2s = d2 + dz - 2;
            bool v12 = ((unsigned)d1s < (unsigned)D1) && ((unsigned)d2s < (unsigned)D2);
            __syncthreads();
            // stage input rows (zero-padded halo), layout [c4][srow][d4p]
            {
                long gb = ((long)((b * D1 + d1s) * D2 + d2s)) * (D3 * D4 * C4);
                for (int i = tid; i < SIN4; i += NTHR) {
                    int d4p = i % 36;
                    int r   = (i / 36) % SROWS;
                    int c4  = i / (36 * SROWS);
                    int d3s = d3b + r - 2;
                    float4 v = make_float4(0.f, 0.f, 0.f, 0.f);
                    if (v12 && (unsigned)d3s < (unsigned)D3 && d4p >= 2 && d4p < 34)
                        v = in4[gb + (d3s * D4 + d4p - 2) * C4 + c4];
                    s_in[i] = v;
                }
            }
            // stage weight slab (contiguous)
            {
                const float4* wsrc = wt4 + (dt * 5 + dz) * (SWF / 4);
                for (int i = tid; i < SWF / 4; i += NTHR) ((float4*)s_w)[i] = wsrc[i];
            }
            __syncthreads();

#pragma unroll 1
            for (int dy = 0; dy < 5; dy++) {
#pragma unroll 1
                for (int dx = 0; dx < 5; dx++) {
                    const float* wtap = s_w + (dy * 5 + dx) * (CIN * COUT) + cb;
#pragma unroll 1
                    for (int c4 = 0; c4 < C4; c4++) {
                        ull ap[4][4];
#pragma unroll
                        for (int j = 0; j < 4; j++) {
                            float4 a = s_in[(c4 * SROWS + rbase + j + dy) * 36 + d4 + dx];
                            ap[j][0] = pack2(a.x); ap[j][1] = pack2(a.y);
                            ap[j][2] = pack2(a.z); ap[j][3] = pack2(a.w);
                        }
#pragma unroll
                        for (int ci = 0; ci < 4; ci++) {
                            const ulonglong2* wrow =
                                (const ulonglong2*)(wtap + (c4 * 4 + ci) * COUT);
#pragma unroll
                            for (int k = 0; k < COUT_T / 4; k++) {
                                ulonglong2 wv = wrow[k];   // broadcast LDS.128
#pragma unroll
                                for (int j = 0; j < 4; j++) {
                                    acc[j][2 * k]     = ffma2(ap[j][ci], wv.x, acc[j][2 * k]);
                                    acc[j][2 * k + 1] = ffma2(ap[j][ci], wv.y, acc[j][2 * k + 1]);
                                }
                            }
                        }
                    }
                }
            }
        }
    }

    // epilogue store
    {
        long obase = ((long)(((b * D1 + d1) * D2 + d2)) * D3) * D4 * COUT;
#pragma unroll
        for (int j = 0; j < 4; j++) {
            int d3 = d3b + rbase + j;
            float4* op = (float4*)(out + obase + ((long)d3 * D4 + d4) * COUT + cb);
#pragma unroll
            for (int k = 0; k < COUT_T / 4; k++) {
                U2F4 u;
                u.u[0] = acc[j][2 * k];
                u.u[1] = acc[j][2 * k + 1];
                op[k] = u.f;
            }
        }
    }
}

// ---------------- batchnorm ----------------
template <int C>
__global__ void bn_stats_kernel(const float* __restrict__ buf, double* __restrict__ sum,
                                double* __restrict__ ssq) {
    __shared__ float s_s[C], s_q[C];
    int tid = threadIdx.x;
    if (tid < C) { s_s[tid] = 0.f; s_q[tid] = 0.f; }
    __syncthreads();
    int gid    = blockIdx.x * blockDim.x + tid;
    int stride = gridDim.x * blockDim.x;
    int ch     = gid % C;
    float ls = 0.f, lq = 0.f;
    for (int i = gid; i < NV * C; i += stride) {
        float v = buf[i];
        ls += v;
        lq += v * v;
    }
    atomicAdd(&s_s[ch], ls);
    atomicAdd(&s_q[ch], lq);
    __syncthreads();
    if (tid < C) {
        atomicAdd(&sum[tid], (double)s_s[tid]);
        atomicAdd(&ssq[tid], (double)s_q[tid]);
    }
}

template <int C>
__global__ void bn_apply_kernel(float* __restrict__ buf, const double* __restrict__ sum,
                                const double* __restrict__ ssq, const float* __restrict__ gamma,
                                const float* __restrict__ beta) {
    __shared__ float sc[C], sh[C];
    int tid = threadIdx.x;
    if (tid < C) {
        double m   = sum[tid] / (double)NV;
        double var = ssq[tid] / (double)NV - m * m;
        double inv = 1.0 / sqrt(var + 1e-5);
        float s = gamma[tid] * (float)inv;
        sc[tid] = s;
        sh[tid] = beta[tid] - (float)m * s;
    }
    __syncthreads();
    int gid    = blockIdx.x * blockDim.x + tid;
    int stride = gridDim.x * blockDim.x;
    float4* b4 = (float4*)buf;
    for (int i = gid; i < NV * C / 4; i += stride) {
        float4 v = b4[i];
        int c0 = (i * 4) % C;
        v.x = v.x * sc[c0]     + sh[c0];
        v.y = v.y * sc[c0 + 1] + sh[c0 + 1];
        v.z = v.z * sc[c0 + 2] + sh[c0 + 2];
        v.w = v.w * sc[c0 + 3] + sh[c0 + 3];
        v.x = fmaxf(v.x, LRELU * v.x);
        v.y = fmaxf(v.y, LRELU * v.y);
        v.z = fmaxf(v.z, LRELU * v.z);
        v.w = fmaxf(v.w, LRELU * v.w);
        b4[i] = v;
    }
}

// ---------------- projection ----------------
__global__ void proj_kernel(const float* __restrict__ buf, const float* __restrict__ wp,
                            const float* __restrict__ bp, float* __restrict__ out) {
    __shared__ float sw[H];
    __shared__ float sb;
    if (threadIdx.x < H) sw[threadIdx.x] = wp[threadIdx.x];
    if (threadIdx.x == 0) sb = bp[0];
    __syncthreads();
    int v = blockIdx.x * blockDim.x + threadIdx.x;
    if (v >= NV) return;
    const float4* hp = (const float4*)(buf + v * H);
    float a = sb;
#pragma unroll
    for (int k = 0; k < 4; k++) {
        float4 h4 = hp[k];
        a += h4.x * sw[4*k] + h4.y * sw[4*k+1] + h4.z * sw[4*k+2] + h4.w * sw[4*k+3];
    }
    out[v] = a;
}

// ---------------- launch ----------------
extern "C" void kernel_launch(void* const* d_in, const int* in_sizes, int n_in,
                              void* d_out, int out_size) {
    const float* x      = (const float*)d_in[0];
    const float* w_emb  = (const float*)d_in[1];
    const float* b_emb  = (const float*)d_in[2];
    const float* W1     = (const float*)d_in[3];
    const float* b1     = (const float*)d_in[4];
    const float* g1     = (const float*)d_in[5];
    const float* be1    = (const float*)d_in[6];
    const float* W2     = (const float*)d_in[7];
    const float* b2     = (const float*)d_in[8];
    const float* g2     = (const float*)d_in[9];
    const float* be2    = (const float*)d_in[10];
    const float* W3     = (const float*)d_in[11];
    const float* b3     = (const float*)d_in[12];
    const float* g3     = (const float*)d_in[13];
    const float* be3    = (const float*)d_in[14];
    const float* w_proj = (const float*)d_in[15];
    const float* b_proj = (const float*)d_in[16];

    float *bufA, *bufB, *bufC, *w1t, *w2t, *w3t;
    double *sums, *ssqs;
    cudaGetSymbolAddress((void**)&bufA, g_bufA);
    cudaGetSymbolAddress((void**)&bufB, g_bufB);
    cudaGetSymbolAddress((void**)&bufC, g_bufC);
    cudaGetSymbolAddress((void**)&w1t, g_W1t);
    cudaGetSymbolAddress((void**)&w2t, g_W2t);
    cudaGetSymbolAddress((void**)&w3t, g_W3t);
    cudaGetSymbolAddress((void**)&sums, g_sum);
    cudaGetSymbolAddress((void**)&ssqs, g_ssq);

    // smem budgets:
    // conv1 <16,16,16,4>:  in 4*20*36*16 = 46080  + w 25600 = 71680
    // conv2 <16,32,16,8>:  in 46080 + w 51200 = 97280
    // conv3 <32,16,32,8>:  in 8*36*36*16 = 165888 + w 51200 = 217088
    cudaFuncSetAttribute(conv4d_kernel<16, 16, 16, 4>, cudaFuncAttributeMaxDynamicSharedMemorySize, 71680);
    cudaFuncSetAttribute(conv4d_kernel<16, 32, 16, 8>, cudaFuncAttributeMaxDynamicSharedMemorySize, 97280);
    cudaFuncSetAttribute(conv4d_kernel<32, 16, 32, 8>, cudaFuncAttributeMaxDynamicSharedMemorySize, 217088);

    zero_stats_kernel<<<1, 128>>>(sums, ssqs);
    reorder_w_kernel<<<(625 * 16 * 16 + 255) / 256, 256>>>(W1, w1t, 16, 16);
    reorder_w_kernel<<<(625 * 16 * 32 + 255) / 256, 256>>>(W2, w2t, 16, 32);
    reorder_w_kernel<<<(625 * 32 * 16 + 255) / 256, 256>>>(W3, w3t, 32, 16);

    embed_kernel<<<NV / 256, 256>>>(x, w_emb, b_emb, bufA);

    conv4d_kernel<16, 16, 16, 4><<<512, 128, 71680>>>(bufA, w1t, b1, bufB);
    bn_stats_kernel<16><<<512, 256>>>(bufB, sums + 0, ssqs + 0);
    bn_apply_kernel<16><<<1024, 256>>>(bufB, sums + 0, ssqs + 0, g1, be1);

    conv4d_kernel<16, 32, 16, 8><<<512, 256, 97280>>>(bufB, w2t, b2, bufC);
    bn_stats_kernel<32><<<512, 256>>>(bufC, sums + 32, ssqs + 32);
    bn_apply_kernel<32><<<1024, 256>>>(bufC, sums + 32, ssqs + 32, g2, be2);

    conv4d_kernel<32, 16, 32, 8><<<256, 256, 217088>>>(bufC, w3t, b3, bufA);
    bn_stats_kernel<16><<<512, 256>>>(bufA, sums + 64, ssqs + 64);
    bn_apply_kernel<16><<<1024, 256>>>(bufA, sums + 64, ssqs + 64, g3, be3);

    proj_kernel<<<NV / 256, 256>>>(bufA, w_proj, b_proj, (float*)d_out);
}

// round 4
// speedup vs baseline: 1.0002x; 1.0002x over previous
#include <cuda_runtime.h>

// ---------------- problem dims ----------------
constexpr int B = 2, D1 = 8, D2 = 16, D3 = 32, D4 = 32, F = 8, H = 16, H2 = 32;
constexpr int NV = B * D1 * D2 * D3 * D4;  // 262144 voxels
constexpr float LRELU = 0.01f;

typedef unsigned long long ull;

// ---------------- static scratch (no allocation allowed) ----------------
__device__ float g_bufA[NV * H];     // embed out / conv3 out
__device__ float g_bufB[NV * H];     // conv1 out
__device__ float g_bufC[NV * H2];    // conv2 out
__device__ float g_W1t[625 * H * H];
__device__ float g_W2t[625 * H * H2];
__device__ float g_W3t[625 * H2 * H];
__device__ double g_sum[3 * 32];
__device__ double g_ssq[3 * 32];

// ---------------- f32x2 helpers (FFMA2 is PTX-only on sm_103a) ----------------
__device__ __forceinline__ ull ffma2(ull a, ull b, ull c) {
    ull d;
    asm("fma.rn.f32x2 %0, %1, %2, %3;" : "=l"(d) : "l"(a), "l"(b), "l"(c));
    return d;
}
__device__ __forceinline__ ull pack2(float x) {
    ull r;
    asm("mov.b64 %0, {%1, %1};" : "=l"(r) : "f"(x));
    return r;
}

union U2F4 { ull u[2]; float4 f; };

// ---------------- small kernels ----------------
__global__ void zero_stats_kernel(double* s, double* q) {
    int i = threadIdx.x;
    if (i < 96) { s[i] = 0.0; q[i] = 0.0; }
}

// W[cout][cin][625] -> Wt[tap][cin][cout]
__global__ void reorder_w_kernel(const float* __restrict__ src, float* __restrict__ dst,
                                 int CIN, int COUT) {
    int n = 625 * CIN * COUT;
    int i = blockIdx.x * blockDim.x + threadIdx.x;
    if (i >= n) return;
    int co  = i % COUT;
    int ci  = (i / COUT) % CIN;
    int tap = i / (COUT * CIN);
    dst[i] = src[(co * CIN + ci) * 625 + tap];
}

// h[v][h16] = x[v][f8] @ w_emb[f][h] + b_emb
__global__ void embed_kernel(const float* __restrict__ x, const float* __restrict__ we,
                             const float* __restrict__ be, float* __restrict__ out) {
    __shared__ float sw[F * H];
    __shared__ float sb[H];
    if (threadIdx.x < F * H) sw[threadIdx.x] = we[threadIdx.x];
    if (threadIdx.x < H) sb[threadIdx.x] = be[threadIdx.x];
    __syncthreads();
    int v = blockIdx.x * blockDim.x + threadIdx.x;
    if (v >= NV) return;
    float xf[F];
    const float4* xp = (const float4*)(x + v * F);
    float4 x0 = xp[0], x1 = xp[1];
    xf[0]=x0.x; xf[1]=x0.y; xf[2]=x0.z; xf[3]=x0.w;
    xf[4]=x1.x; xf[5]=x1.y; xf[6]=x1.z; xf[7]=x1.w;
    float o[H];
#pragma unroll
    for (int h = 0; h < H; h++) {
        float a = sb[h];
#pragma unroll
        for (int f = 0; f < F; f++) a += xf[f] * sw[f * H + h];
        o[h] = a;
    }
    float4* op = (float4*)(out + v * H);
#pragma unroll
    for (int k = 0; k < 4; k++) op[k] = make_float4(o[4*k], o[4*k+1], o[4*k+2], o[4*k+3]);
}

// ---------------- 4D conv (FFMA2, register-resident couts) ----------------
// Block covers (b, d1, d2) x BROWS d3-rows x all 32 d4.
// Warp: 32 lanes = d4; rg = row-quad (4 d3 rows), ch = cout-half.
// Each thread accumulates 4 rows x COUT_T(16) couts as 32 f32x2 pairs.
// s_in layout [c4][srow][36 d4pad] (float4) -> per-lane LDS.128 conflict-free.
// Weight LDS are warp-uniform broadcasts.
template <int CIN, int COUT, int BROWS, int NW>
__global__ void __launch_bounds__(NW * 32)
conv4d_kernel(const float* __restrict__ in, const float* __restrict__ wt,
              const float* __restrict__ bias, float* __restrict__ out) {
    constexpr int C4    = CIN / 4;
    constexpr int SROWS = BROWS + 4;
    constexpr int NRG   = BROWS / 4;
    constexpr int NCH   = NW / NRG;
    constexpr int COUT_T = COUT / NCH;            // 16
    constexpr int NTHR  = NW * 32;
    constexpr int SIN4  = C4 * SROWS * 36;        // float4 count
    constexpr int SWF   = 25 * CIN * COUT;        // floats per (dt,dz) slab
    constexpr int DB3   = D3 / BROWS;

    extern __shared__ float smem[];
    float4* s_in = (float4*)smem;                 // [c4][srow][36]
    float*  s_w  = smem + SIN4 * 4;               // [tap25][ci][cout]

    int bi   = blockIdx.x;
    int d3b  = (bi % DB3) * BROWS;
    int rest = bi / DB3;
    int d2 = rest & 15, d1 = (rest >> 4) & 7, b = rest >> 7;

    int tid  = threadIdx.x;
    int wid  = tid >> 5, lane = tid & 31;
    int rg   = wid % NRG, ch = wid / NRG;
    int cb   = ch * COUT_T;
    int d4   = lane;
    int rbase = rg * 4;

    ull acc[4][COUT_T / 2];
    {
        const ull* bp = (const ull*)(bias + cb);
#pragma unroll
        for (int j = 0; j < 4; j++)
#pragma unroll
            for (int p = 0; p < COUT_T / 2; p++) acc[j][p] = bp[p];
    }

    const float4* in4 = (const float4*)in;
    const float4* wt4 = (const float4*)wt;

    for (int dt = 0; dt < 5; dt++) {
        int d1s = d1 + dt - 2;
        for (int dz = 0; dz < 5; dz++) {
            int d2s = d2 + dz - 2;
            bool v12 = ((unsigned)d1s < (unsigned)D1) && ((unsigned)d2s < (unsigned)D2);
            __syncthreads();
            // stage input rows (zero-padded halo), layout [c4][srow][d4p]
            {
                long gb = ((long)((b * D1 + d1s) * D2 + d2s)) * (D3 * D4 * C4);
                for (int i = tid; i < SIN4; i += NTHR) {
                    int d4p = i % 36;
                    int r   = (i / 36) % SROWS;
                    int c4  = i / (36 * SROWS);
                    int d3s = d3b + r - 2;
                    float4 v = make_float4(0.f, 0.f, 0.f, 0.f);
                    if (v12 && (unsigned)d3s < (unsigned)D3 && d4p >= 2 && d4p < 34)
                        v = in4[gb + (d3s * D4 + d4p - 2) * C4 + c4];
                    s_in[i] = v;
                }
            }
            // stage weight slab (contiguous)
            {
                const float4* wsrc = wt4 + (dt * 5 + dz) * (SWF / 4);
                for (int i = tid; i < SWF / 4; i += NTHR) ((float4*)s_w)[i] = wsrc[i];
            }
            __syncthreads();

#pragma unroll 1
            for (int dy = 0; dy < 5; dy++) {
#pragma unroll 1
                for (int dx = 0; dx < 5; dx++) {
                    const float* wtap = s_w + (dy * 5 + dx) * (CIN * COUT) + cb;
#pragma unroll 1
                    for (int c4 = 0; c4 < C4; c4++) {
                        ull ap[4][4];
#pragma unroll
                        for (int j = 0; j < 4; j++) {
                            float4 a = s_in[(c4 * SROWS + rbase + j + dy) * 36 + d4 + dx];
                            ap[j][0] = pack2(a.x); ap[j][1] = pack2(a.y);
                            ap[j][2] = pack2(a.z); ap[j][3] = pack2(a.w);
                        }
#pragma unroll
                        for (int ci = 0; ci < 4; ci++) {
                            const ulonglong2* wrow =
                                (const ulonglong2*)(wtap + (c4 * 4 + ci) * COUT);
#pragma unroll
                            for (int k = 0; k < COUT_T / 4; k++) {
                                ulonglong2 wv = wrow[k];   // broadcast LDS.128
#pragma unroll
                                for (int j = 0; j < 4; j++) {
                                    acc[j][2 * k]     = ffma2(ap[j][ci], wv.x, acc[j][2 * k]);
                                    acc[j][2 * k + 1] = ffma2(ap[j][ci], wv.y, acc[j][2 * k + 1]);
                                }
                            }
                        }
                    }
                }
            }
        }
    }

    // epilogue store
    {
        long obase = ((long)(((b * D1 + d1) * D2 + d2)) * D3) * D4 * COUT;
#pragma unroll
        for (int j = 0; j < 4; j++) {
            int d3 = d3b + rbase + j;
            float4* op = (float4*)(out + obase + ((long)d3 * D4 + d4) * COUT + cb);
#pragma unroll
            for (int k = 0; k < COUT_T / 4; k++) {
                U2F4 u;
                u.u[0] = acc[j][2 * k];
                u.u[1] = acc[j][2 * k + 1];
                op[k] = u.f;
            }
        }
    }
}

// ---------------- batchnorm ----------------
template <int C>
__global__ void bn_stats_kernel(const float* __restrict__ buf, double* __restrict__ sum,
                                double* __restrict__ ssq) {
    __shared__ float s_s[C], s_q[C];
    int tid = threadIdx.x;
    if (tid < C) { s_s[tid] = 0.f; s_q[tid] = 0.f; }
    __syncthreads();
    int gid    = blockIdx.x * blockDim.x + tid;
    int stride = gridDim.x * blockDim.x;
    int ch     = gid % C;
    float ls = 0.f, lq = 0.f;
    for (int i = gid; i < NV * C; i += stride) {
        float v = buf[i];
        ls += v;
        lq += v * v;
    }
    atomicAdd(&s_s[ch], ls);
    atomicAdd(&s_q[ch], lq);
    __syncthreads();
    if (tid < C) {
        atomicAdd(&sum[tid], (double)s_s[tid]);
        atomicAdd(&ssq[tid], (double)s_q[tid]);
    }
}

template <int C>
__global__ void bn_apply_kernel(float* __restrict__ buf, const double* __restrict__ sum,
                                const double* __restrict__ ssq, const float* __restrict__ gamma,
                                const float* __restrict__ beta) {
    __shared__ float sc[C], sh[C];
    int tid = threadIdx.x;
    if (tid < C) {
        double m   = sum[tid] / (double)NV;
        double var = ssq[tid] / (double)NV - m * m;
        double inv = 1.0 / sqrt(var + 1e-5);
        float s = gamma[tid] * (float)inv;
        sc[tid] = s;
        sh[tid] = beta[tid] - (float)m * s;
    }
    __syncthreads();
    int gid    = blockIdx.x * blockDim.x + tid;
    int stride = gridDim.x * blockDim.x;
    float4* b4 = (float4*)buf;
    for (int i = gid; i < NV * C / 4; i += stride) {
        float4 v = b4[i];
        int c0 = (i * 4) % C;
        v.x = v.x * sc[c0]     + sh[c0];
        v.y = v.y * sc[c0 + 1] + sh[c0 + 1];
        v.z = v.z * sc[c0 + 2] + sh[c0 + 2];
        v.w = v.w * sc[c0 + 3] + sh[c0 + 3];
        v.x = fmaxf(v.x, LRELU * v.x);
        v.y = fmaxf(v.y, LRELU * v.y);
        v.z = fmaxf(v.z, LRELU * v.z);
        v.w = fmaxf(v.w, LRELU * v.w);
        b4[i] = v;
    }
}

// ---------------- projection ----------------
__global__ void proj_kernel(const float* __restrict__ buf, const float* __restrict__ wp,
                            const float* __restrict__ bp, float* __restrict__ out) {
    __shared__ float sw[H];
    __shared__ float sb;
    if (threadIdx.x < H) sw[threadIdx.x] = wp[threadIdx.x];
    if (threadIdx.x == 0) sb = bp[0];
    __syncthreads();
    int v = blockIdx.x * blockDim.x + threadIdx.x;
    if (v >= NV) return;
    const float4* hp = (const float4*)(buf + v * H);
    float a = sb;
#pragma unroll
    for (int k = 0; k < 4; k++) {
        float4 h4 = hp[k];
        a += h4.x * sw[4*k] + h4.y * sw[4*k+1] + h4.z * sw[4*k+2] + h4.w * sw[4*k+3];
    }
    out[v] = a;
}

// ---------------- launch ----------------
extern "C" void kernel_launch(void* const* d_in, const int* in_sizes, int n_in,
                              void* d_out, int out_size) {
    const float* x      = (const float*)d_in[0];
    const float* w_emb  = (const float*)d_in[1];
    const float* b_emb  = (const float*)d_in[2];
    const float* W1     = (const float*)d_in[3];
    const float* b1     = (const float*)d_in[4];
    const float* g1     = (const float*)d_in[5];
    const float* be1    = (const float*)d_in[6];
    const float* W2     = (const float*)d_in[7];
    const float* b2     = (const float*)d_in[8];
    const float* g2     = (const float*)d_in[9];
    const float* be2    = (const float*)d_in[10];
    const float* W3     = (const float*)d_in[11];
    const float* b3     = (const float*)d_in[12];
    const float* g3     = (const float*)d_in[13];
    const float* be3    = (const float*)d_in[14];
    const float* w_proj = (const float*)d_in[15];
    const float* b_proj = (const float*)d_in[16];

    float *bufA, *bufB, *bufC, *w1t, *w2t, *w3t;
    double *sums, *ssqs;
    cudaGetSymbolAddress((void**)&bufA, g_bufA);
    cudaGetSymbolAddress((void**)&bufB, g_bufB);
    cudaGetSymbolAddress((void**)&bufC, g_bufC);
    cudaGetSymbolAddress((void**)&w1t, g_W1t);
    cudaGetSymbolAddress((void**)&w2t, g_W2t);
    cudaGetSymbolAddress((void**)&w3t, g_W3t);
    cudaGetSymbolAddress((void**)&sums, g_sum);
    cudaGetSymbolAddress((void**)&ssqs, g_ssq);

    // smem budgets:
    // conv1 <16,16,16,4>:  in 4*20*36*16 = 46080  + w 25600 = 71680
    // conv2 <16,32,16,8>:  in 46080 + w 51200 = 97280
    // conv3 <32,16,32,8>:  in 8*36*36*16 = 165888 + w 51200 = 217088
    cudaFuncSetAttribute(conv4d_kernel<16, 16, 16, 4>, cudaFuncAttributeMaxDynamicSharedMemorySize, 71680);
    cudaFuncSetAttribute(conv4d_kernel<16, 32, 16, 8>, cudaFuncAttributeMaxDynamicSharedMemorySize, 97280);
    cudaFuncSetAttribute(conv4d_kernel<32, 16, 32, 8>, cudaFuncAttributeMaxDynamicSharedMemorySize, 217088);

    zero_stats_kernel<<<1, 128>>>(sums, ssqs);
    reorder_w_kernel<<<(625 * 16 * 16 + 255) / 256, 256>>>(W1, w1t, 16, 16);
    reorder_w_kernel<<<(625 * 16 * 32 + 255) / 256, 256>>>(W2, w2t, 16, 32);
    reorder_w_kernel<<<(625 * 32 * 16 + 255) / 256, 256>>>(W3, w3t, 32, 16);

    embed_kernel<<<NV / 256, 256>>>(x, w_emb, b_emb, bufA);

    conv4d_kernel<16, 16, 16, 4><<<512, 128, 71680>>>(bufA, w1t, b1, bufB);
    bn_stats_kernel<16><<<512, 256>>>(bufB, sums + 0, ssqs + 0);
    bn_apply_kernel<16><<<1024, 256>>>(bufB, sums + 0, ssqs + 0, g1, be1);

    conv4d_kernel<16, 32, 16, 8><<<512, 256, 97280>>>(bufB, w2t, b2, bufC);
    bn_stats_kernel<32><<<512, 256>>>(bufC, sums + 32, ssqs + 32);
    bn_apply_kernel<32><<<1024, 256>>>(bufC, sums + 32, ssqs + 32, g2, be2);

    conv4d_kernel<32, 16, 32, 8><<<256, 256, 217088>>>(bufC, w3t, b3, bufA);
    bn_stats_kernel<16><<<512, 256>>>(bufA, sums + 64, ssqs + 64);
    bn_apply_kernel<16><<<1024, 256>>>(bufA, sums + 64, ssqs + 64, g3, be3);

    proj_kernel<<<NV / 256, 256>>>(bufA, w_proj, b_proj, (float*)d_out);
}

// round 5
// speedup vs baseline: 1.0004x; 1.0002x over previous
#include <cuda_runtime.h>

// ---------------- problem dims ----------------
constexpr int B = 2, D1 = 8, D2 = 16, D3 = 32, D4 = 32, F = 8, H = 16, H2 = 32;
constexpr int NV = B * D1 * D2 * D3 * D4;  // 262144 voxels
constexpr float LRELU = 0.01f;

typedef unsigned long long ull;

// ---------------- static scratch (no allocation allowed) ----------------
__device__ float g_bufA[NV * H];     // embed out / conv3 out
__device__ float g_bufB[NV * H];     // conv1 out
__device__ float g_bufC[NV * H2];    // conv2 out
__device__ float g_W1t[625 * H * H];
__device__ float g_W2t[625 * H * H2];
__device__ float g_W3t[625 * H2 * H];
__device__ double g_sum[3 * 32];
__device__ double g_ssq[3 * 32];

// ---------------- f32x2 helpers (FFMA2 is PTX-only on sm_103a) ----------------
__device__ __forceinline__ ull ffma2(ull a, ull b, ull c) {
    ull d;
    asm("fma.rn.f32x2 %0, %1, %2, %3;" : "=l"(d) : "l"(a), "l"(b), "l"(c));
    return d;
}
__device__ __forceinline__ ull pack2(float x) {
    ull r;
    asm("mov.b64 %0, {%1, %1};" : "=l"(r) : "f"(x));
    return r;
}

union U2F4 { ull u[2]; float4 f; };

// ---------------- small kernels ----------------
__global__ void zero_stats_kernel(double* s, double* q) {
    int i = threadIdx.x;
    if (i < 96) { s[i] = 0.0; q[i] = 0.0; }
}

// W[cout][cin][625] -> Wt[tap][cin][cout]
__global__ void reorder_w_kernel(const float* __restrict__ src, float* __restrict__ dst,
                                 int CIN, int COUT) {
    int n = 625 * CIN * COUT;
    int i = blockIdx.x * blockDim.x + threadIdx.x;
    if (i >= n) return;
    int co  = i % COUT;
    int ci  = (i / COUT) % CIN;
    int tap = i / (COUT * CIN);
    dst[i] = src[(co * CIN + ci) * 625 + tap];
}

// h[v][h16] = x[v][f8] @ w_emb[f][h] + b_emb
__global__ void embed_kernel(const float* __restrict__ x, const float* __restrict__ we,
                             const float* __restrict__ be, float* __restrict__ out) {
    __shared__ float sw[F * H];
    __shared__ float sb[H];
    if (threadIdx.x < F * H) sw[threadIdx.x] = we[threadIdx.x];
    if (threadIdx.x < H) sb[threadIdx.x] = be[threadIdx.x];
    __syncthreads();
    int v = blockIdx.x * blockDim.x + threadIdx.x;
    if (v >= NV) return;
    float xf[F];
    const float4* xp = (const float4*)(x + v * F);
    float4 x0 = xp[0], x1 = xp[1];
    xf[0]=x0.x; xf[1]=x0.y; xf[2]=x0.z; xf[3]=x0.w;
    xf[4]=x1.x; xf[5]=x1.y; xf[6]=x1.z; xf[7]=x1.w;
    float o[H];
#pragma unroll
    for (int h = 0; h < H; h++) {
        float a = sb[h];
#pragma unroll
        for (int f = 0; f < F; f++) a += xf[f] * sw[f * H + h];
        o[h] = a;
    }
    float4* op = (float4*)(out + v * H);
#pragma unroll
    for (int k = 0; k < 4; k++) op[k] = make_float4(o[4*k], o[4*k+1], o[4*k+2], o[4*k+3]);
}

// ---------------- 4D conv (FFMA2, register-resident couts) ----------------
// Block covers (b, d1, d2) x BROWS d3-rows x all 32 d4.
// Warp: 32 lanes = d4; rg = row-quad (4 d3 rows), ch = cout-half.
// Each thread accumulates 4 rows x COUT_T(16) couts as 32 f32x2 pairs.
// s_in layout [c4][srow][36 d4pad] (float4) -> per-lane LDS.128 conflict-free.
// Weight LDS are warp-uniform broadcasts.
template <int CIN, int COUT, int BROWS, int NW>
__global__ void __launch_bounds__(NW * 32)
conv4d_kernel(const float* __restrict__ in, const float* __restrict__ wt,
              const float* __restrict__ bias, float* __restrict__ out) {
    constexpr int C4    = CIN / 4;
    constexpr int SROWS = BROWS + 4;
    constexpr int NRG   = BROWS / 4;
    constexpr int NCH   = NW / NRG;
    constexpr int COUT_T = COUT / NCH;            // 16
    constexpr int NTHR  = NW * 32;
    constexpr int SIN4  = C4 * SROWS * 36;        // float4 count
    constexpr int SWF   = 25 * CIN * COUT;        // floats per (dt,dz) slab
    constexpr int DB3   = D3 / BROWS;

    extern __shared__ float smem[];
    float4* s_in = (float4*)smem;                 // [c4][srow][36]
    float*  s_w  = smem + SIN4 * 4;               // [tap25][ci][cout]

    int bi   = blockIdx.x;
    int d3b  = (bi % DB3) * BROWS;
    int rest = bi / DB3;
    int d2 = rest & 15, d1 = (rest >> 4) & 7, b = rest >> 7;

    int tid  = threadIdx.x;
    int wid  = tid >> 5, lane = tid & 31;
    int rg   = wid % NRG, ch = wid / NRG;
    int cb   = ch * COUT_T;
    int d4   = lane;
    int rbase = rg * 4;

    ull acc[4][COUT_T / 2];
    {
        const ull* bp = (const ull*)(bias + cb);
#pragma unroll
        for (int j = 0; j < 4; j++)
#pragma unroll
            for (int p = 0; p < COUT_T / 2; p++) acc[j][p] = bp[p];
    }

    const float4* in4 = (const float4*)in;
    const float4* wt4 = (const float4*)wt;

    for (int dt = 0; dt < 5; dt++) {
        int d1s = d1 + dt - 2;
        for (int dz = 0; dz < 5; dz++) {
            int d2s = d2 + dz - 2;
            bool v12 = ((unsigned)d1s < (unsigned)D1) && ((unsigned)d2s < (unsigned)D2);
            __syncthreads();
            // stage input rows (zero-padded halo), layout [c4][srow][d4p]
            {
                long gb = ((long)((b * D1 + d1s) * D2 + d2s)) * (D3 * D4 * C4);
                for (int i = tid; i < SIN4; i += NTHR) {
                    int d4p = i % 36;
                    int r   = (i / 36) % SROWS;
                    int c4  = i / (36 * SROWS);
                    int d3s = d3b + r - 2;
                    float4 v = make_float4(0.f, 0.f, 0.f, 0.f);
                    if (v12 && (unsigned)d3s < (unsigned)D3 && d4p >= 2 && d4p < 34)
                        v = in4[gb + (d3s * D4 + d4p - 2) * C4 + c4];
                    s_in[i] = v;
                }
            }
            // stage weight slab (contiguous)
            {
                const float4* wsrc = wt4 + (dt * 5 + dz) * (SWF / 4);
                for (int i = tid; i < SWF / 4; i += NTHR) ((float4*)s_w)[i] = wsrc[i];
            }
            __syncthreads();

#pragma unroll 1
            for (int dy = 0; dy < 5; dy++) {
#pragma unroll 1
                for (int dx = 0; dx < 5; dx++) {
                    const float* wtap = s_w + (dy * 5 + dx) * (CIN * COUT) + cb;
#pragma unroll 1
                    for (int c4 = 0; c4 < C4; c4++) {
                        ull ap[4][4];
#pragma unroll
                        for (int j = 0; j < 4; j++) {
                            float4 a = s_in[(c4 * SROWS + rbase + j + dy) * 36 + d4 + dx];
                            ap[j][0] = pack2(a.x); ap[j][1] = pack2(a.y);
                            ap[j][2] = pack2(a.z); ap[j][3] = pack2(a.w);
                        }
#pragma unroll
                        for (int ci = 0; ci < 4; ci++) {
                            const ulonglong2* wrow =
                                (const ulonglong2*)(wtap + (c4 * 4 + ci) * COUT);
#pragma unroll
                            for (int k = 0; k < COUT_T / 4; k++) {
                                ulonglong2 wv = wrow[k];   // broadcast LDS.128
#pragma unroll
                                for (int j = 0; j < 4; j++) {
                                    acc[j][2 * k]     = ffma2(ap[j][ci], wv.x, acc[j][2 * k]);
                                    acc[j][2 * k + 1] = ffma2(ap[j][ci], wv.y, acc[j][2 * k + 1]);
                                }
                            }
                        }
                    }
                }
            }
        }
    }

    // epilogue store
    {
        long obase = ((long)(((b * D1 + d1) * D2 + d2)) * D3) * D4 * COUT;
#pragma unroll
        for (int j = 0; j < 4; j++) {
            int d3 = d3b + rbase + j;
            float4* op = (float4*)(out + obase + ((long)d3 * D4 + d4) * COUT + cb);
#pragma unroll
            for (int k = 0; k < COUT_T / 4; k++) {
                U2F4 u;
                u.u[0] = acc[j][2 * k];
                u.u[1] = acc[j][2 * k + 1];
                op[k] = u.f;
            }
        }
    }
}

// ---------------- batchnorm ----------------
template <int C>
__global__ void bn_stats_kernel(const float* __restrict__ buf, double* __restrict__ sum,
                                double* __restrict__ ssq) {
    __shared__ float s_s[C], s_q[C];
    int tid = threadIdx.x;
    if (tid < C) { s_s[tid] = 0.f; s_q[tid] = 0.f; }
    __syncthreads();
    int gid    = blockIdx.x * blockDim.x + tid;
    int stride = gridDim.x * blockDim.x;
    int ch     = gid % C;
    float ls = 0.f, lq = 0.f;
    for (int i = gid; i < NV * C; i += stride) {
        float v = buf[i];
        ls += v;
        lq += v * v;
    }
    atomicAdd(&s_s[ch], ls);
    atomicAdd(&s_q[ch], lq);
    __syncthreads();
    if (tid < C) {
        atomicAdd(&sum[tid], (double)s_s[tid]);
        atomicAdd(&ssq[tid], (double)s_q[tid]);
    }
}

template <int C>
__global__ void bn_apply_kernel(float* __restrict__ buf, const double* __restrict__ sum,
                                const double* __restrict__ ssq, const float* __restrict__ gamma,
                                const float* __restrict__ beta) {
    __shared__ float sc[C], sh[C];
    int tid = threadIdx.x;
    if (tid < C) {
        double m   = sum[tid] / (double)NV;
        double var = ssq[tid] / (double)NV - m * m;
        double inv = 1.0 / sqrt(var + 1e-5);
        float s = gamma[tid] * (float)inv;
        sc[tid] = s;
        sh[tid] = beta[tid] - (float)m * s;
    }
    __syncthreads();
    int gid    = blockIdx.x * blockDim.x + tid;
    int stride = gridDim.x * blockDim.x;
    float4* b4 = (float4*)buf;
    for (int i = gid; i < NV * C / 4; i += stride) {
        float4 v = b4[i];
        int c0 = (i * 4) % C;
        v.x = v.x * sc[c0]     + sh[c0];
        v.y = v.y * sc[c0 + 1] + sh[c0 + 1];
        v.z = v.z * sc[c0 + 2] + sh[c0 + 2];
        v.w = v.w * sc[c0 + 3] + sh[c0 + 3];
        v.x = fmaxf(v.x, LRELU * v.x);
        v.y = fmaxf(v.y, LRELU * v.y);
        v.z = fmaxf(v.z, LRELU * v.z);
        v.w = fmaxf(v.w, LRELU * v.w);
        b4[i] = v;
    }
}

// ---------------- projection ----------------
__global__ void proj_kernel(const float* __restrict__ buf, const float* __restrict__ wp,
                            const float* __restrict__ bp, float* __restrict__ out) {
    __shared__ float sw[H];
    __shared__ float sb;
    if (threadIdx.x < H) sw[threadIdx.x] = wp[threadIdx.x];
    if (threadIdx.x == 0) sb = bp[0];
    __syncthreads();
    int v = blockIdx.x * blockDim.x + threadIdx.x;
    if (v >= NV) return;
    const float4* hp = (const float4*)(buf + v * H);
    float a = sb;
#pragma unroll
    for (int k = 0; k < 4; k++) {
        float4 h4 = hp[k];
        a += h4.x * sw[4*k] + h4.y * sw[4*k+1] + h4.z * sw[4*k+2] + h4.w * sw[4*k+3];
    }
    out[v] = a;
}

// ---------------- launch ----------------
extern "C" void kernel_launch(void* const* d_in, const int* in_sizes, int n_in,
                              void* d_out, int out_size) {
    const float* x      = (const float*)d_in[0];
    const float* w_emb  = (const float*)d_in[1];
    const float* b_emb  = (const float*)d_in[2];
    const float* W1     = (const float*)d_in[3];
    const float* b1     = (const float*)d_in[4];
    const float* g1     = (const float*)d_in[5];
    const float* be1    = (const float*)d_in[6];
    const float* W2     = (const float*)d_in[7];
    const float* b2     = (const float*)d_in[8];
    const float* g2     = (const float*)d_in[9];
    const float* be2    = (const float*)d_in[10];
    const float* W3     = (const float*)d_in[11];
    const float* b3     = (const float*)d_in[12];
    const float* g3     = (const float*)d_in[13];
    const float* be3    = (const float*)d_in[14];
    const float* w_proj = (const float*)d_in[15];
    const float* b_proj = (const float*)d_in[16];

    float *bufA, *bufB, *bufC, *w1t, *w2t, *w3t;
    double *sums, *ssqs;
    cudaGetSymbolAddress((void**)&bufA, g_bufA);
    cudaGetSymbolAddress((void**)&bufB, g_bufB);
    cudaGetSymbolAddress((void**)&bufC, g_bufC);
    cudaGetSymbolAddress((void**)&w1t, g_W1t);
    cudaGetSymbolAddress((void**)&w2t, g_W2t);
    cudaGetSymbolAddress((void**)&w3t, g_W3t);
    cudaGetSymbolAddress((void**)&sums, g_sum);
    cudaGetSymbolAddress((void**)&ssqs, g_ssq);

    // smem budgets:
    // conv1 <16,16,16,4>:  in 4*20*36*16 = 46080  + w 25600 = 71680
    // conv2 <16,32,16,8>:  in 46080 + w 51200 = 97280
    // conv3 <32,16,32,8>:  in 8*36*36*16 = 165888 + w 51200 = 217088
    cudaFuncSetAttribute(conv4d_kernel<16, 16, 16, 4>, cudaFuncAttributeMaxDynamicSharedMemorySize, 71680);
    cudaFuncSetAttribute(conv4d_kernel<16, 32, 16, 8>, cudaFuncAttributeMaxDynamicSharedMemorySize, 97280);
    cudaFuncSetAttribute(conv4d_kernel<32, 16, 32, 8>, cudaFuncAttributeMaxDynamicSharedMemorySize, 217088);

    zero_stats_kernel<<<1, 128>>>(sums, ssqs);
    reorder_w_kernel<<<(625 * 16 * 16 + 255) / 256, 256>>>(W1, w1t, 16, 16);
    reorder_w_kernel<<<(625 * 16 * 32 + 255) / 256, 256>>>(W2, w2t, 16, 32);
    reorder_w_kernel<<<(625 * 32 * 16 + 255) / 256, 256>>>(W3, w3t, 32, 16);

    embed_kernel<<<NV / 256, 256>>>(x, w_emb, b_emb, bufA);

    conv4d_kernel<16, 16, 16, 4><<<512, 128, 71680>>>(bufA, w1t, b1, bufB);
    bn_stats_kernel<16><<<512, 256>>>(bufB, sums + 0, ssqs + 0);
    bn_apply_kernel<16><<<1024, 256>>>(bufB, sums + 0, ssqs + 0, g1, be1);

    conv4d_kernel<16, 32, 16, 8><<<512, 256, 97280>>>(bufB, w2t, b2, bufC);
    bn_stats_kernel<32><<<512, 256>>>(bufC, sums + 32, ssqs + 32);
    bn_apply_kernel<32><<<1024, 256>>>(bufC, sums + 32, ssqs + 32, g2, be2);

    conv4d_kernel<32, 16, 32, 8><<<256, 256, 217088>>>(bufC, w3t, b3, bufA);
    bn_stats_kernel<16><<<512, 256>>>(bufA, sums + 64, ssqs + 64);
    bn_apply_kernel<16><<<1024, 256>>>(bufA, sums + 64, ssqs + 64, g3, be3);

    proj_kernel<<<NV / 256, 256>>>(bufA, w_proj, b_proj, (float*)d_out);
}

// round 6
// speedup vs baseline: 1.2596x; 1.2591x over previous
#include <cuda_runtime.h>
#include <cuda_bf16.h>

// ---------------- problem dims ----------------
constexpr int B = 2, D1 = 8, D2 = 16, D3 = 32, D4 = 32, F = 8, H = 16, H2 = 32;
constexpr int NV = B * D1 * D2 * D3 * D4;  // 262144 voxels
constexpr float LRELU = 0.01f;

// ---------------- static scratch (no allocation allowed) ----------------
// activation triples: per 16-channel plane, per voxel: 48 bf16 = [t0:ah(16)][t1:al(16)][t2:ah(16)]
__device__ __nv_bfloat16 g_actA[(long)NV * 48];   // conv1 input / conv3-bn output (proj input)
__device__ __nv_bfloat16 g_actB[(long)NV * 48];   // conv2 input
__device__ __nv_bfloat16 g_actC[(long)NV * 96];   // conv3 input (2 planes)
__device__ float g_fout[(long)NV * 32];           // conv fp32 output (reused)
// expanded weights: [slab][dy][cout][dx*48 + t*16 + ci]
__device__ __nv_bfloat16 g_wx1[25 * 5 * 16 * 240];
__device__ __nv_bfloat16 g_wx2[25 * 5 * 32 * 240];
__device__ __nv_bfloat16 g_wx3[50 * 5 * 16 * 240];
__device__ double g_sum[3 * 32];
__device__ double g_ssq[3 * 32];

// ---------------- helpers ----------------
__device__ __forceinline__ unsigned pack_bf2(float lo, float hi) {
    __nv_bfloat162 t = __floats2bfloat162_rn(lo, hi);
    return *(unsigned*)&t;
}
__device__ __forceinline__ void split_bf(float v, float& hi_f, __nv_bfloat16& hi, __nv_bfloat16& lo) {
    hi = __float2bfloat16(v);
    hi_f = __bfloat162float(hi);
    lo = __float2bfloat16(v - hi_f);
}
__device__ __forceinline__ void mma16816(float* c, unsigned a0, unsigned a1, unsigned a2, unsigned a3,
                                         unsigned b0, unsigned b1) {
    asm volatile(
        "mma.sync.aligned.m16n8k16.row.col.f32.bf16.bf16.f32 "
        "{%0,%1,%2,%3},{%4,%5,%6,%7},{%8,%9},{%0,%1,%2,%3};"
        : "+f"(c[0]), "+f"(c[1]), "+f"(c[2]), "+f"(c[3])
        : "r"(a0), "r"(a1), "r"(a2), "r"(a3), "r"(b0), "r"(b1));
}

// ---------------- small kernels ----------------
__global__ void zero_stats_kernel(double* s, double* q) {
    int i = threadIdx.x;
    if (i < 96) { s[i] = 0.0; q[i] = 0.0; }
}

// expand W[cout][cin][625] -> wext[s][dy][co][dx*48 + t*16 + ci]
__global__ void wext_kernel(const float* __restrict__ W, __nv_bfloat16* __restrict__ dst,
                            int COUT, int CINF, int n) {
    int i = blockIdx.x * blockDim.x + threadIdx.x;
    if (i >= n) return;
    int ci = i % 16;
    int t  = (i / 16) % 3;
    int dx = (i / 48) % 5;
    int co = (i / 240) % COUT;
    int dy = (i / (240 * COUT)) % 5;
    int s  = i / (1200 * COUT);
    int g = s / 25, tap = s % 25, dt = tap / 5, dz = tap % 5;
    float w = W[(co * CINF + g * 16 + ci) * 625 + dt * 125 + dz * 25 + dy * 5 + dx];
    __nv_bfloat16 wh = __float2bfloat16(w);
    __nv_bfloat16 out;
    if (t == 2) out = __float2bfloat16(w - __bfloat162float(wh));
    else out = wh;
    dst[i] = out;
}

// embed: h[16] = x[f8] @ w_emb + b_emb, write split triple to actA
__global__ void embed_kernel(const float* __restrict__ x, const float* __restrict__ we,
                             const float* __restrict__ be, __nv_bfloat16* __restrict__ act) {
    __shared__ float sw[F * H];
    __shared__ float sb[H];
    if (threadIdx.x < F * H) sw[threadIdx.x] = we[threadIdx.x];
    if (threadIdx.x < H) sb[threadIdx.x] = be[threadIdx.x];
    __syncthreads();
    int v = blockIdx.x * blockDim.x + threadIdx.x;
    if (v >= NV) return;
    const float4* xp = (const float4*)(x + v * F);
    float4 x0 = xp[0], x1 = xp[1];
    float xf[F] = {x0.x, x0.y, x0.z, x0.w, x1.x, x1.y, x1.z, x1.w};
    float o[H];
#pragma unroll
    for (int h = 0; h < H; h++) {
        float a = sb[h];
#pragma unroll
        for (int f = 0; f < F; f++) a += xf[f] * sw[f * H + h];
        o[h] = a;
    }
    unsigned hw[8], lw[8];
#pragma unroll
    for (int p = 0; p < 8; p++) {
        float hf0, hf1; __nv_bfloat16 h0, l0, h1, l1;
        split_bf(o[2 * p], hf0, h0, l0);
        split_bf(o[2 * p + 1], hf1, h1, l1);
        __nv_bfloat162 hh; hh.x = h0; hh.y = h1;
        __nv_bfloat162 ll; ll.x = l0; ll.y = l1;
        hw[p] = *(unsigned*)&hh;
        lw[p] = *(unsigned*)&ll;
    }
    uint4* dst = (uint4*)(act + (long)v * 48);
    dst[0] = make_uint4(hw[0], hw[1], hw[2], hw[3]);
    dst[1] = make_uint4(hw[4], hw[5], hw[6], hw[7]);
    dst[2] = make_uint4(lw[0], lw[1], lw[2], lw[3]);
    dst[3] = make_uint4(lw[4], lw[5], lw[6], lw[7]);
    dst[4] = dst[0];
    dst[5] = dst[1];
}

// ---------------- tensor-core 4D conv ----------------
// CTA = (b,d1,d2) x 8 d3-rows, M=256 voxels. 8 warps, each owns m16-tiles wid and wid+8.
// K folded: per (dt,dz) slab, per dy: 5dx * 48(triple-cin) = 240 contiguous k.
template <int COUT, int SLABS>
__global__ void __launch_bounds__(256)
conv_mma_kernel(const __nv_bfloat16* __restrict__ act, const __nv_bfloat16* __restrict__ wext,
                const float* __restrict__ bias, float* __restrict__ fout) {
    constexpr int NT = COUT / 8;
    constexpr int SA_U32 = 12 * 36 * 24;      // 10368 u32 (12 srows x 36 d4p x 48 bf16)
    constexpr int SW_U4  = COUT * 150;        // u4 count of one slab's weights
    extern __shared__ unsigned smem_u[];
    unsigned* sA = smem_u;
    unsigned* sW = smem_u + SA_U32;

    int bi = blockIdx.x;
    int d3b = (bi & 3) * 8;
    int rest = bi >> 2;
    int d2 = rest & 15, d1 = (rest >> 4) & 7, b = rest >> 7;

    int tid = threadIdx.x, lane = tid & 31, wid = tid >> 5;
    int d3r0 = wid >> 1, h = wid & 1, d3r1 = d3r0 + 4;
    int lq = lane >> 2, lr = lane & 3;

    float acc[2][NT][4];
#pragma unroll
    for (int t = 0; t < 2; t++)
#pragma unroll
        for (int n = 0; n < NT; n++) {
            float b0 = bias[n * 8 + 2 * lr], b1v = bias[n * 8 + 2 * lr + 1];
            acc[t][n][0] = b0; acc[t][n][1] = b1v; acc[t][n][2] = b0; acc[t][n][3] = b1v;
        }

    const uint4* actu4 = (const uint4*)act;
    const uint4* wxu4  = (const uint4*)wext;

    for (int s = 0; s < SLABS; s++) {
        int g = s / 25, tap = s % 25;
        int dt = tap / 5, dz = tap % 5;
        int d1s = d1 + dt - 2, d2s = d2 + dz - 2;
        bool v12 = ((unsigned)d1s < 8u) && ((unsigned)d2s < 16u);
        int pbase = g * (NV * 6);
        int vb = ((b * 8 + d1s) * 16 + d2s) * 1024;
        __syncthreads();
        // stage A: 12 srows x 36 d4p x 6 u4
        for (int i = tid; i < 2592; i += 256) {
            int srow = i / 216, r2 = i % 216;
            int d4p = r2 / 6, q = r2 % 6;
            int d3s = d3b + srow - 2;
            uint4 v = make_uint4(0, 0, 0, 0);
            if (v12 && (unsigned)d3s < 32u && d4p >= 2 && d4p < 34)
                v = actu4[pbase + (vb + d3s * 32 + d4p - 2) * 6 + q];
            ((uint4*)sA)[i] = v;
        }
        // stage W slab (contiguous)
        {
            const uint4* wsrc = wxu4 + (long)s * SW_U4;
            for (int i = tid; i < SW_U4; i += 256) ((uint4*)sW)[i] = wsrc[i];
        }
        __syncthreads();

#pragma unroll 1
        for (int dy = 0; dy < 5; dy++) {
            int a0b = ((d3r0 + dy) * 36 + h * 16 + lq) * 24 + lr;
            int a1b = ((d3r1 + dy) * 36 + h * 16 + lq) * 24 + lr;
            int bb  = (dy * COUT + lq) * 120 + lr;
#pragma unroll 1
            for (int kc = 0; kc < 15; kc++) {
                int k8 = kc * 8;
                unsigned a00 = sA[a0b + k8],       a01 = sA[a0b + 192 + k8];
                unsigned a02 = sA[a0b + k8 + 4],   a03 = sA[a0b + 192 + k8 + 4];
                unsigned a10 = sA[a1b + k8],       a11 = sA[a1b + 192 + k8];
                unsigned a12 = sA[a1b + k8 + 4],   a13 = sA[a1b + 192 + k8 + 4];
#pragma unroll
                for (int n = 0; n < NT; n++) {
                    unsigned b0 = sW[bb + n * 960 + k8];
                    unsigned b1 = sW[bb + n * 960 + k8 + 4];
                    mma16816(acc[0][n], a00, a01, a02, a03, b0, b1);
                    mma16816(acc[1][n], a10, a11, a12, a13, b0, b1);
                }
            }
        }
    }

    // epilogue: store fp32 [vox][COUT]
    int vox0 = ((b * 8 + d1) * 16 + d2) * 1024 + d3b * 32;
#pragma unroll
    for (int t = 0; t < 2; t++) {
        int d3r = t ? d3r1 : d3r0;
        long base = (long)(vox0 + d3r * 32 + h * 16 + lq) * COUT + 2 * lr;
#pragma unroll
        for (int n = 0; n < NT; n++) {
            *(float2*)&fout[base + n * 8]              = make_float2(acc[t][n][0], acc[t][n][1]);
            *(float2*)&fout[base + 8 * COUT + n * 8]   = make_float2(acc[t][n][2], acc[t][n][3]);
        }
    }
}

// ---------------- batchnorm ----------------
template <int C>
__global__ void bn_stats_kernel(const float* __restrict__ buf, double* __restrict__ sum,
                                double* __restrict__ ssq) {
    __shared__ float s_s[C], s_q[C];
    int tid = threadIdx.x;
    if (tid < C) { s_s[tid] = 0.f; s_q[tid] = 0.f; }
    __syncthreads();
    int gid    = blockIdx.x * blockDim.x + tid;
    int stride = gridDim.x * blockDim.x;
    int ch     = gid % C;
    float ls = 0.f, lq = 0.f;
    for (long i = gid; i < (long)NV * C; i += stride) {
        float v = buf[i];
        ls += v;
        lq += v * v;
    }
    atomicAdd(&s_s[ch], ls);
    atomicAdd(&s_q[ch], lq);
    __syncthreads();
    if (tid < C) {
        atomicAdd(&sum[tid], (double)s_s[tid]);
        atomicAdd(&ssq[tid], (double)s_q[tid]);
    }
}

// bn + leaky-relu + bf16 split-triple write (C/16 planes of NV*48)
template <int C>
__global__ void bn_apply_kernel(const float* __restrict__ fout, const double* __restrict__ sum,
                                const double* __restrict__ ssq, const float* __restrict__ gamma,
                                const float* __restrict__ beta, __nv_bfloat16* __restrict__ act) {
    constexpr int NPL = C / 16;
    __shared__ float sc[C], sh[C];
    int tid = threadIdx.x;
    if (tid < C) {
        double m   = sum[tid] / (double)NV;
        double var = ssq[tid] / (double)NV - m * m;
        double inv = 1.0 / sqrt(var + 1e-5);
        float s = gamma[tid] * (float)inv;
        sc[tid] = s;
        sh[tid] = beta[tid] - (float)m * s;
    }
    __syncthreads();
    long total  = (long)NV * NPL;
    long stride = (long)gridDim.x * blockDim.x;
    for (long id = blockIdx.x * (long)blockDim.x + tid; id < total; id += stride) {
        int vox = (int)(id % NV);
        int pl  = (int)(id / NV);
        const float4* src = (const float4*)&fout[(long)vox * C + pl * 16];
        float vv[16];
        float4 v0 = src[0], v1 = src[1], v2 = src[2], v3 = src[3];
        vv[0]=v0.x; vv[1]=v0.y; vv[2]=v0.z; vv[3]=v0.w;
        vv[4]=v1.x; vv[5]=v1.y; vv[6]=v1.z; vv[7]=v1.w;
        vv[8]=v2.x; vv[9]=v2.y; vv[10]=v2.z; vv[11]=v2.w;
        vv[12]=v3.x; vv[13]=v3.y; vv[14]=v3.z; vv[15]=v3.w;
        unsigned hw[8], lw[8];
#pragma unroll
        for (int p = 0; p < 8; p++) {
            float r0 = vv[2*p]   * sc[pl*16 + 2*p]   + sh[pl*16 + 2*p];
            float r1 = vv[2*p+1] * sc[pl*16 + 2*p+1] + sh[pl*16 + 2*p+1];
            r0 = fmaxf(r0, LRELU * r0);
            r1 = fmaxf(r1, LRELU * r1);
            float hf0, hf1; __nv_bfloat16 h0, l0, h1, l1;
            split_bf(r0, hf0, h0, l0);
            split_bf(r1, hf1, h1, l1);
            __nv_bfloat162 hh; hh.x = h0; hh.y = h1;
            __nv_bfloat162 ll; ll.x = l0; ll.y = l1;
            hw[p] = *(unsigned*)&hh;
            lw[p] = *(unsigned*)&ll;
        }
        uint4* dst = (uint4*)&act[((long)pl * NV + vox) * 48];
        uint4 u0 = make_uint4(hw[0], hw[1], hw[2], hw[3]);
        uint4 u1 = make_uint4(hw[4], hw[5], hw[6], hw[7]);
        dst[0] = u0;
        dst[1] = u1;
        dst[2] = make_uint4(lw[0], lw[1], lw[2], lw[3]);
        dst[3] = make_uint4(lw[4], lw[5], lw[6], lw[7]);
        dst[4] = u0;
        dst[5] = u1;
    }
}

// ---------------- projection (reads triple: a = hi + lo) ----------------
__global__ void proj_kernel(const __nv_bfloat16* __restrict__ act, const float* __restrict__ wp,
                            const float* __restrict__ bp, float* __restrict__ out) {
    __shared__ float sw[H];
    __shared__ float sb;
    if (threadIdx.x < H) sw[threadIdx.x] = wp[threadIdx.x];
    if (threadIdx.x == 0) sb = bp[0];
    __syncthreads();
    int v = blockIdx.x * blockDim.x + threadIdx.x;
    if (v >= NV) return;
    const uint4* ap = (const uint4*)(act + (long)v * 48);
    uint4 uh0 = ap[0], uh1 = ap[1], ul0 = ap[2], ul1 = ap[3];
    unsigned hu[8] = {uh0.x, uh0.y, uh0.z, uh0.w, uh1.x, uh1.y, uh1.z, uh1.w};
    unsigned lu[8] = {ul0.x, ul0.y, ul0.z, ul0.w, ul1.x, ul1.y, ul1.z, ul1.w};
    float a = sb;
#pragma unroll
    for (int p = 0; p < 8; p++) {
        __nv_bfloat162 hh = *(__nv_bfloat162*)&hu[p];
        __nv_bfloat162 ll = *(__nv_bfloat162*)&lu[p];
        float a0 = __bfloat162float(hh.x) + __bfloat162float(ll.x);
        float a1 = __bfloat162float(hh.y) + __bfloat162float(ll.y);
        a += a0 * sw[2*p] + a1 * sw[2*p+1];
    }
    out[v] = a;
}

// ---------------- launch ----------------
extern "C" void kernel_launch(void* const* d_in, const int* in_sizes, int n_in,
                              void* d_out, int out_size) {
    const float* x      = (const float*)d_in[0];
    const float* w_emb  = (const float*)d_in[1];
    const float* b_emb  = (const float*)d_in[2];
    const float* W1     = (const float*)d_in[3];
    const float* b1     = (const float*)d_in[4];
    const float* g1     = (const float*)d_in[5];
    const float* be1    = (const float*)d_in[6];
    const float* W2     = (const float*)d_in[7];
    const float* b2     = (const float*)d_in[8];
    const float* g2     = (const float*)d_in[9];
    const float* be2    = (const float*)d_in[10];
    const float* W3     = (const float*)d_in[11];
    const float* b3     = (const float*)d_in[12];
    const float* g3     = (const float*)d_in[13];
    const float* be3    = (const float*)d_in[14];
    const float* w_proj = (const float*)d_in[15];
    const float* b_proj = (const float*)d_in[16];

    __nv_bfloat16 *actA, *actB, *actC, *wx1, *wx2, *wx3;
    float* fout;
    double *sums, *ssqs;
    cudaGetSymbolAddress((void**)&actA, g_actA);
    cudaGetSymbolAddress((void**)&actB, g_actB);
    cudaGetSymbolAddress((void**)&actC, g_actC);
    cudaGetSymbolAddress((void**)&fout, g_fout);
    cudaGetSymbolAddress((void**)&wx1, g_wx1);
    cudaGetSymbolAddress((void**)&wx2, g_wx2);
    cudaGetSymbolAddress((void**)&wx3, g_wx3);
    cudaGetSymbolAddress((void**)&sums, g_sum);
    cudaGetSymbolAddress((void**)&ssqs, g_ssq);

    // smem: A 41472 B + W slab (COUT*2400 B)
    cudaFuncSetAttribute(conv_mma_kernel<16, 25>, cudaFuncAttributeMaxDynamicSharedMemorySize, 41472 + 38400);
    cudaFuncSetAttribute(conv_mma_kernel<32, 25>, cudaFuncAttributeMaxDynamicSharedMemorySize, 41472 + 76800);
    cudaFuncSetAttribute(conv_mma_kernel<16, 50>, cudaFuncAttributeMaxDynamicSharedMemorySize, 41472 + 38400);

    zero_stats_kernel<<<1, 128>>>(sums, ssqs);
    wext_kernel<<<(480000 + 255) / 256, 256>>>(W1, wx1, 16, 16, 480000);
    wext_kernel<<<(960000 + 255) / 256, 256>>>(W2, wx2, 32, 16, 960000);
    wext_kernel<<<(960000 + 255) / 256, 256>>>(W3, wx3, 16, 32, 960000);

    embed_kernel<<<NV / 256, 256>>>(x, w_emb, b_emb, actA);

    conv_mma_kernel<16, 25><<<1024, 256, 41472 + 38400>>>(actA, wx1, b1, fout);
    bn_stats_kernel<16><<<512, 256>>>(fout, sums + 0, ssqs + 0);
    bn_apply_kernel<16><<<1024, 256>>>(fout, sums + 0, ssqs + 0, g1, be1, actB);

    conv_mma_kernel<32, 25><<<1024, 256, 41472 + 76800>>>(actB, wx2, b2, fout);
    bn_stats_kernel<32><<<512, 256>>>(fout, sums + 32, ssqs + 32);
    bn_apply_kernel<32><<<1024, 256>>>(fout, sums + 32, ssqs + 32, g2, be2, actC);

    conv_mma_kernel<16, 50><<<1024, 256, 41472 + 38400>>>(actC, wx3, b3, fout);
    bn_stats_kernel<16><<<512, 256>>>(fout, sums + 64, ssqs + 64);
    bn_apply_kernel<16><<<1024, 256>>>(fout, sums + 64, ssqs + 64, g3, be3, actA);

    proj_kernel<<<NV / 256, 256>>>(actA, w_proj, b_proj, (float*)d_out);
}

// round 7
// speedup vs baseline: 3.1121x; 2.4708x over previous
#include <cuda_runtime.h>
#include <cuda_bf16.h>

// ---------------- problem dims ----------------
constexpr int B = 2, D1 = 8, D2 = 16, D3 = 32, D4 = 32, F = 8, H = 16, H2 = 32;
constexpr int NV = B * D1 * D2 * D3 * D4;  // 262144 voxels
constexpr float LRELU = 0.01f;

// ---------------- static scratch (no allocation allowed) ----------------
// activations: tf32-rounded fp32, plane-major [plane16][vox][16ch]
__device__ unsigned g_actA[(long)NV * 16];        // conv1 input / conv3-bn out (proj in)
__device__ unsigned g_actB[(long)NV * 16];        // conv2 input
__device__ unsigned g_actC[(long)NV * 32];        // conv3 input (2 planes)
__device__ float    g_fout[(long)NV * 32];        // conv fp32 output (reused)
// expanded weights (tf32-rounded): [slab][dy][cout][84]  (k = dx*16+ci in 0..79, pad to 84)
__device__ unsigned g_wx1[25 * 5 * 16 * 84];
__device__ unsigned g_wx2[25 * 5 * 32 * 84];
__device__ unsigned g_wx3[50 * 5 * 16 * 84];
__device__ double g_sum[3 * 32];
__device__ double g_ssq[3 * 32];

// ---------------- helpers ----------------
__device__ __forceinline__ unsigned f2tf(float f) {
    unsigned u;
    asm("cvt.rna.tf32.f32 %0, %1;" : "=r"(u) : "f"(f));
    return u;
}
__device__ __forceinline__ void mma_tf32(float* c, unsigned a0, unsigned a1, unsigned a2, unsigned a3,
                                         unsigned b0, unsigned b1) {
    asm volatile(
        "mma.sync.aligned.m16n8k8.row.col.f32.tf32.tf32.f32 "
        "{%0,%1,%2,%3},{%4,%5,%6,%7},{%8,%9},{%0,%1,%2,%3};"
        : "+f"(c[0]), "+f"(c[1]), "+f"(c[2]), "+f"(c[3])
        : "r"(a0), "r"(a1), "r"(a2), "r"(a3), "r"(b0), "r"(b1));
}

// ---------------- small kernels ----------------
__global__ void zero_stats_kernel(double* s, double* q) {
    int i = threadIdx.x;
    if (i < 96) { s[i] = 0.0; q[i] = 0.0; }
}

// expand W[cout][cinF][625] -> [slab][dy][co][84] tf32
__global__ void wext_kernel(const float* __restrict__ W, unsigned* __restrict__ dst,
                            int COUT, int CINF, int n) {
    int i = blockIdx.x * blockDim.x + threadIdx.x;
    if (i >= n) return;
    int k  = i % 84;
    int co = (i / 84) % COUT;
    int dy = (i / (84 * COUT)) % 5;
    int s  = i / (420 * COUT);
    int g = s / 25, tap = s % 25, dt = tap / 5, dz = tap % 5;
    unsigned val = 0;
    if (k < 80) {
        int dx = k / 16, ci = k % 16;
        float w = W[(co * CINF + g * 16 + ci) * 625 + dt * 125 + dz * 25 + dy * 5 + dx];
        val = f2tf(w);
    }
    dst[i] = val;
}

// embed: h[16] = x[f8] @ w_emb + b_emb, tf32-rounded fp32 out
__global__ void embed_kernel(const float* __restrict__ x, const float* __restrict__ we,
                             const float* __restrict__ be, unsigned* __restrict__ act) {
    __shared__ float sw[F * H];
    __shared__ float sb[H];
    if (threadIdx.x < F * H) sw[threadIdx.x] = we[threadIdx.x];
    if (threadIdx.x < H) sb[threadIdx.x] = be[threadIdx.x];
    __syncthreads();
    int v = blockIdx.x * blockDim.x + threadIdx.x;
    if (v >= NV) return;
    const float4* xp = (const float4*)(x + v * F);
    float4 x0 = xp[0], x1 = xp[1];
    float xf[F] = {x0.x, x0.y, x0.z, x0.w, x1.x, x1.y, x1.z, x1.w};
    unsigned o[H];
#pragma unroll
    for (int h = 0; h < H; h++) {
        float a = sb[h];
#pragma unroll
        for (int f = 0; f < F; f++) a += xf[f] * sw[f * H + h];
        o[h] = f2tf(a);
    }
    uint4* dst = (uint4*)(act + (long)v * 16);
#pragma unroll
    for (int q = 0; q < 4; q++) dst[q] = make_uint4(o[4*q], o[4*q+1], o[4*q+2], o[4*q+3]);
}

// ---------------- tensor-core 4D conv (tf32, single pass) ----------------
// CTA = (b,d1,d2) x 8 d3-rows, M=256 voxels. 8 warps x 2 m16-tiles.
// A smem: [srow12][d4p36] pitch 20 u32 (16 ch + 4 pad) -> conflict-free LDS.
// K per dy = 80 (5 dx * 16 ci), contiguous via d4p fold: k-chunk kc: dx=kc>>1, ci=(kc&1)*8+lr.
template <int COUT, int SLABS>
__global__ void __launch_bounds__(256)
conv_mma_kernel(const unsigned* __restrict__ act, const unsigned* __restrict__ wext,
                const float* __restrict__ bias, float* __restrict__ fout) {
    constexpr int NT = COUT / 8;
    constexpr int SA_U32 = 12 * 36 * 20;          // 8640
    constexpr int SW_U32 = 5 * COUT * 84;         // whole slab (all dy)
    extern __shared__ unsigned smem_u[];
    unsigned* sA = smem_u;
    unsigned* sW = smem_u + SA_U32;

    int bi = blockIdx.x;
    int d3b = (bi & 3) * 8;
    int rest = bi >> 2;
    int d2 = rest & 15, d1 = (rest >> 4) & 7, b = rest >> 7;

    int tid = threadIdx.x, lane = tid & 31, wid = tid >> 5;
    int d3r0 = wid >> 1, h = wid & 1;
    int lq = lane >> 2, lr = lane & 3;

    float acc[2][NT][4];
#pragma unroll
    for (int t = 0; t < 2; t++)
#pragma unroll
        for (int n = 0; n < NT; n++) {
            float b0 = bias[n * 8 + 2 * lr], b1v = bias[n * 8 + 2 * lr + 1];
            acc[t][n][0] = b0; acc[t][n][1] = b1v; acc[t][n][2] = b0; acc[t][n][3] = b1v;
        }

    const uint4* actu4 = (const uint4*)act;
    const uint4* wxu4  = (const uint4*)wext;

    for (int s = 0; s < SLABS; s++) {
        int g = s / 25, tap = s % 25;
        int dt = tap / 5, dz = tap % 5;
        int d1s = d1 + dt - 2, d2s = d2 + dz - 2;
        bool v12 = ((unsigned)d1s < 8u) && ((unsigned)d2s < 16u);
        int pbase = g * NV;                       // plane voxel offset
        int vb = ((b * 8 + d1s) * 16 + d2s) * 1024;
        __syncthreads();
        // stage A: 12 srows x 36 d4p x 4 uint4
        for (int i = tid; i < 1728; i += 256) {
            int q = i & 3;
            int d4p = (i >> 2) % 36;
            int srow = i / 144;
            int d3s = d3b + srow - 2;
            uint4 v = make_uint4(0, 0, 0, 0);
            if (v12 && (unsigned)d3s < 32u && d4p >= 2 && d4p < 34)
                v = actu4[((long)(pbase + vb + d3s * 32 + d4p - 2) << 2) + q];
            *(uint4*)(sA + (srow * 36 + d4p) * 20 + q * 4) = v;
        }
        // stage W slab (contiguous)
        {
            const uint4* wsrc = wxu4 + (long)s * (SW_U32 / 4);
            for (int i = tid; i < SW_U32 / 4; i += 256) ((uint4*)sW)[i] = wsrc[i];
        }
        __syncthreads();

#pragma unroll 1
        for (int dy = 0; dy < 5; dy++) {
            int arow0 = ((d3r0 + dy) * 36 + h * 16 + lq) * 20 + lr;
            int arow1 = arow0 + 2880;             // d3r1 = d3r0 + 4 -> +4*36*20
            int wb = dy * (COUT * 84) + lq * 84 + lr;
#pragma unroll
            for (int kc = 0; kc < 10; kc++) {
                int koff = (kc >> 1) * 20 + (kc & 1) * 8;
                unsigned a00 = sA[arow0 + koff],       a02 = sA[arow0 + koff + 4];
                unsigned a01 = sA[arow0 + 160 + koff], a03 = sA[arow0 + 160 + koff + 4];
                unsigned a10 = sA[arow1 + koff],       a12 = sA[arow1 + koff + 4];
                unsigned a11 = sA[arow1 + 160 + koff], a13 = sA[arow1 + 160 + koff + 4];
#pragma unroll
                for (int n = 0; n < NT; n++) {
                    unsigned b0 = sW[wb + n * 672 + kc * 8];
                    unsigned b1 = sW[wb + n * 672 + kc * 8 + 4];
                    mma_tf32(acc[0][n], a00, a01, a02, a03, b0, b1);
                    mma_tf32(acc[1][n], a10, a11, a12, a13, b0, b1);
                }
            }
        }
    }

    // epilogue: store fp32 [vox][COUT]
    int vox0 = ((b * 8 + d1) * 16 + d2) * 1024 + d3b * 32;
#pragma unroll
    for (int t = 0; t < 2; t++) {
        int d3r = (t ? d3r0 + 4 : d3r0);
        long base = (long)(vox0 + d3r * 32 + h * 16 + lq) * COUT + 2 * lr;
#pragma unroll
        for (int n = 0; n < NT; n++) {
            *(float2*)&fout[base + n * 8]            = make_float2(acc[t][n][0], acc[t][n][1]);
            *(float2*)&fout[base + 8 * COUT + n * 8] = make_float2(acc[t][n][2], acc[t][n][3]);
        }
    }
}

// ---------------- batchnorm ----------------
template <int C>
__global__ void bn_stats_kernel(const float* __restrict__ buf, double* __restrict__ sum,
                                double* __restrict__ ssq) {
    __shared__ float s_s[C], s_q[C];
    int tid = threadIdx.x;
    if (tid < C) { s_s[tid] = 0.f; s_q[tid] = 0.f; }
    __syncthreads();
    int gid    = blockIdx.x * blockDim.x + tid;
    int stride = gridDim.x * blockDim.x;
    int ch     = gid % C;
    float ls = 0.f, lq = 0.f;
    for (long i = gid; i < (long)NV * C; i += stride) {
        float v = buf[i];
        ls += v;
        lq += v * v;
    }
    atomicAdd(&s_s[ch], ls);
    atomicAdd(&s_q[ch], lq);
    __syncthreads();
    if (tid < C) {
        atomicAdd(&sum[tid], (double)s_s[tid]);
        atomicAdd(&ssq[tid], (double)s_q[tid]);
    }
}

// bn + leaky-relu + tf32-rounded fp32 write, plane-major [pl][vox][16]
template <int C>
__global__ void bn_apply_kernel(const float* __restrict__ fout, const double* __restrict__ sum,
                                const double* __restrict__ ssq, const float* __restrict__ gamma,
                                const float* __restrict__ beta, unsigned* __restrict__ act) {
    constexpr int NPL = C / 16;
    __shared__ float sc[C], sh[C];
    int tid = threadIdx.x;
    if (tid < C) {
        double m   = sum[tid] / (double)NV;
        double var = ssq[tid] / (double)NV - m * m;
        double inv = 1.0 / sqrt(var + 1e-5);
        float s = gamma[tid] * (float)inv;
        sc[tid] = s;
        sh[tid] = beta[tid] - (float)m * s;
    }
    __syncthreads();
    long total  = (long)NV * NPL;
    long stride = (long)gridDim.x * blockDim.x;
    for (long id = blockIdx.x * (long)blockDim.x + tid; id < total; id += stride) {
        int vox = (int)(id % NV);
        int pl  = (int)(id / NV);
        const float4* src = (const float4*)&fout[(long)vox * C + pl * 16];
        float4 v0 = src[0], v1 = src[1], v2 = src[2], v3 = src[3];
        float vv[16] = {v0.x, v0.y, v0.z, v0.w, v1.x, v1.y, v1.z, v1.w,
                        v2.x, v2.y, v2.z, v2.w, v3.x, v3.y, v3.z, v3.w};
        unsigned o[16];
#pragma unroll
        for (int c = 0; c < 16; c++) {
            float r = vv[c] * sc[pl * 16 + c] + sh[pl * 16 + c];
            r = fmaxf(r, LRELU * r);
            o[c] = f2tf(r);
        }
        uint4* dst = (uint4*)&act[((long)pl * NV + vox) * 16];
#pragma unroll
        for (int q = 0; q < 4; q++) dst[q] = make_uint4(o[4*q], o[4*q+1], o[4*q+2], o[4*q+3]);
    }
}

// ---------------- projection ----------------
__global__ void proj_kernel(const unsigned* __restrict__ act, const float* __restrict__ wp,
                            const float* __restrict__ bp, float* __restrict__ out) {
    __shared__ float sw[H];
    __shared__ float sb;
    if (threadIdx.x < H) sw[threadIdx.x] = wp[threadIdx.x];
    if (threadIdx.x == 0) sb = bp[0];
    __syncthreads();
    int v = blockIdx.x * blockDim.x + threadIdx.x;
    if (v >= NV) return;
    const uint4* ap = (const uint4*)(act + (long)v * 16);
    float a = sb;
#pragma unroll
    for (int q = 0; q < 4; q++) {
        uint4 u = ap[q];
        a += __uint_as_float(u.x) * sw[4*q]     + __uint_as_float(u.y) * sw[4*q+1]
           + __uint_as_float(u.z) * sw[4*q+2] + __uint_as_float(u.w) * sw[4*q+3];
    }
    out[v] = a;
}

// ---------------- launch ----------------
extern "C" void kernel_launch(void* const* d_in, const int* in_sizes, int n_in,
                              void* d_out, int out_size) {
    const float* x      = (const float*)d_in[0];
    const float* w_emb  = (const float*)d_in[1];
    const float* b_emb  = (const float*)d_in[2];
    const float* W1     = (const float*)d_in[3];
    const float* b1     = (const float*)d_in[4];
    const float* g1     = (const float*)d_in[5];
    const float* be1    = (const float*)d_in[6];
    const float* W2     = (const float*)d_in[7];
    const float* b2     = (const float*)d_in[8];
    const float* g2     = (const float*)d_in[9];
    const float* be2    = (const float*)d_in[10];
    const float* W3     = (const float*)d_in[11];
    const float* b3     = (const float*)d_in[12];
    const float* g3     = (const float*)d_in[13];
    const float* be3    = (const float*)d_in[14];
    const float* w_proj = (const float*)d_in[15];
    const float* b_proj = (const float*)d_in[16];

    unsigned *actA, *actB, *actC, *wx1, *wx2, *wx3;
    float* fout;
    double *sums, *ssqs;
    cudaGetSymbolAddress((void**)&actA, g_actA);
    cudaGetSymbolAddress((void**)&actB, g_actB);
    cudaGetSymbolAddress((void**)&actC, g_actC);
    cudaGetSymbolAddress((void**)&fout, g_fout);
    cudaGetSymbolAddress((void**)&wx1, g_wx1);
    cudaGetSymbolAddress((void**)&wx2, g_wx2);
    cudaGetSymbolAddress((void**)&wx3, g_wx3);
    cudaGetSymbolAddress((void**)&sums, g_sum);
    cudaGetSymbolAddress((void**)&ssqs, g_ssq);

    // smem: A 34560 B + W slab (5*COUT*84*4 B): conv1/3: 61440; conv2: 88320
    cudaFuncSetAttribute(conv_mma_kernel<16, 25>, cudaFuncAttributeMaxDynamicSharedMemorySize, 61440);
    cudaFuncSetAttribute(conv_mma_kernel<32, 25>, cudaFuncAttributeMaxDynamicSharedMemorySize, 88320);
    cudaFuncSetAttribute(conv_mma_kernel<16, 50>, cudaFuncAttributeMaxDynamicSharedMemorySize, 61440);

    zero_stats_kernel<<<1, 128>>>(sums, ssqs);
    wext_kernel<<<(168000 + 255) / 256, 256>>>(W1, wx1, 16, 16, 168000);
    wext_kernel<<<(336000 + 255) / 256, 256>>>(W2, wx2, 32, 16, 336000);
    wext_kernel<<<(336000 + 255) / 256, 256>>>(W3, wx3, 16, 32, 336000);

    embed_kernel<<<NV / 256, 256>>>(x, w_emb, b_emb, actA);

    conv_mma_kernel<16, 25><<<1024, 256, 61440>>>(actA, wx1, b1, fout);
    bn_stats_kernel<16><<<512, 256>>>(fout, sums + 0, ssqs + 0);
    bn_apply_kernel<16><<<1024, 256>>>(fout, sums + 0, ssqs + 0, g1, be1, actB);

    conv_mma_kernel<32, 25><<<1024, 256, 88320>>>(actB, wx2, b2, fout);
    bn_stats_kernel<32><<<512, 256>>>(fout, sums + 32, ssqs + 32);
    bn_apply_kernel<32><<<1024, 256>>>(fout, sums + 32, ssqs + 32, g2, be2, actC);

    conv_mma_kernel<16, 50><<<1024, 256, 61440>>>(actC, wx3, b3, fout);
    bn_stats_kernel<16><<<512, 256>>>(fout, sums + 64, ssqs + 64);
    bn_apply_kernel<16><<<1024, 256>>>(fout, sums + 64, ssqs + 64, g3, be3, actA);

    proj_kernel<<<NV / 256, 256>>>(actA, w_proj, b_proj, (float*)d_out);
}

// round 8
// speedup vs baseline: 6.3568x; 2.0426x over previous
#include <cuda_runtime.h>
#include <cuda_fp16.h>

// ---------------- problem dims ----------------
constexpr int B = 2, D1 = 8, D2 = 16, D3 = 32, D4 = 32, F = 8, H = 16, H2 = 32;
constexpr int NV = B * D1 * D2 * D3 * D4;  // 262144 voxels
constexpr float LRELU = 0.01f;

// ---------------- static scratch ----------------
// activations: fp16, plane-major [plane16ch][vox][16 fp16 = 8 u32]
__device__ unsigned g_actA[(long)NV * 8];         // conv1 input
__device__ unsigned g_actB[(long)NV * 8];         // conv2 input
__device__ unsigned g_actC[(long)NV * 16];        // conv3 input (2 planes)
__device__ float    g_fout[(long)NV * 32];        // conv fp32 output (reused)
// expanded fp16 weights: [slab][dy][cout][44 u32]  (k = dx*16+ci, 80 fp16 = 40 u32 + 4 pad)
__device__ unsigned g_wx1[25 * 5 * 16 * 44];
__device__ unsigned g_wx2[25 * 5 * 32 * 44];
__device__ unsigned g_wx3[50 * 5 * 16 * 44];
__device__ double g_sum[3 * 32];
__device__ double g_ssq[3 * 32];

// ---------------- helpers ----------------
__device__ __forceinline__ unsigned packh2(float a, float b) {
    __half2 h = __floats2half2_rn(a, b);
    return *(unsigned*)&h;
}
__device__ __forceinline__ void mma_f16(float* c, unsigned a0, unsigned a1, unsigned a2, unsigned a3,
                                        unsigned b0, unsigned b1) {
    asm volatile(
        "mma.sync.aligned.m16n8k16.row.col.f32.f16.f16.f32 "
        "{%0,%1,%2,%3},{%4,%5,%6,%7},{%8,%9},{%0,%1,%2,%3};"
        : "+f"(c[0]), "+f"(c[1]), "+f"(c[2]), "+f"(c[3])
        : "r"(a0), "r"(a1), "r"(a2), "r"(a3), "r"(b0), "r"(b1));
}

// ---------------- small kernels ----------------
__global__ void zero_stats_kernel(double* s, double* q) {
    int i = threadIdx.x;
    if (i < 96) { s[i] = 0.0; q[i] = 0.0; }
}

// expand W[cout][cinF][625] -> [slab][dy][co][44 u32] fp16 pairs
__global__ void wext_kernel(const float* __restrict__ W, unsigned* __restrict__ dst,
                            int COUT, int CINF, int n) {
    int i = blockIdx.x * blockDim.x + threadIdx.x;
    if (i >= n) return;
    int j  = i % 44;
    int co = (i / 44) % COUT;
    int dy = (i / (44 * COUT)) % 5;
    int s  = i / (220 * COUT);
    int g = s / 25, tap = s % 25, dt = tap / 5, dz = tap % 5;
    unsigned val = 0;
    if (j < 40) {
        int dx = j / 8, ci = 2 * (j % 8);
        long base = dt * 125 + dz * 25 + dy * 5 + dx;
        float w0 = W[((long)co * CINF + g * 16 + ci) * 625 + base];
        float w1 = W[((long)co * CINF + g * 16 + ci + 1) * 625 + base];
        val = packh2(w0, w1);
    }
    dst[i] = val;
}

// embed: h[16] = x[f8] @ w_emb + b_emb, fp16 out
__global__ void embed_kernel(const float* __restrict__ x, const float* __restrict__ we,
                             const float* __restrict__ be, unsigned* __restrict__ act) {
    __shared__ float sw[F * H];
    __shared__ float sb[H];
    if (threadIdx.x < F * H) sw[threadIdx.x] = we[threadIdx.x];
    if (threadIdx.x < H) sb[threadIdx.x] = be[threadIdx.x];
    __syncthreads();
    int v = blockIdx.x * blockDim.x + threadIdx.x;
    if (v >= NV) return;
    const float4* xp = (const float4*)(x + v * F);
    float4 x0 = xp[0], x1 = xp[1];
    float xf[F] = {x0.x, x0.y, x0.z, x0.w, x1.x, x1.y, x1.z, x1.w};
    float o[H];
#pragma unroll
    for (int h = 0; h < H; h++) {
        float a = sb[h];
#pragma unroll
        for (int f = 0; f < F; f++) a += xf[f] * sw[f * H + h];
        o[h] = a;
    }
    unsigned p[8];
#pragma unroll
    for (int q = 0; q < 8; q++) p[q] = packh2(o[2*q], o[2*q+1]);
    uint4* dst = (uint4*)(act + (long)v * 8);
    dst[0] = make_uint4(p[0], p[1], p[2], p[3]);
    dst[1] = make_uint4(p[4], p[5], p[6], p[7]);
}

// ---------------- tensor-core 4D conv (fp16 k16) + fused BN stats ----------------
// CTA = (b,d1,d2) x 8 d3-rows, M=256 voxels. 8 warps x 2 m16-tiles.
// A smem: [srow12][d4p36] cell = 12 u32 (16 fp16 in slots 0..7, 4 pad) -> conflict-free.
// k per dy = 80 fp16 = 5 k16-chunks; chunk kc == dx.
template <int COUT, int SLABS>
__global__ void __launch_bounds__(256)
conv_mma_kernel(const unsigned* __restrict__ act, const unsigned* __restrict__ wext,
                const float* __restrict__ bias, float* __restrict__ fout,
                double* __restrict__ gsum, double* __restrict__ gssq) {
    constexpr int NT = COUT / 8;
    constexpr int SA_U32 = 12 * 36 * 12;          // 5184
    constexpr int SW_U32 = 5 * COUT * 44;
    extern __shared__ unsigned smem_u[];
    unsigned* sA = smem_u;
    unsigned* sW = smem_u + SA_U32;
    float* s_st  = (float*)(smem_u + SA_U32 + SW_U32);   // [2*COUT]

    int bi = blockIdx.x;
    int d3b = (bi & 3) * 8;
    int rest = bi >> 2;
    int d2 = rest & 15, d1 = (rest >> 4) & 7, b = rest >> 7;

    int tid = threadIdx.x, lane = tid & 31, wid = tid >> 5;
    int d3r0 = wid >> 1, h = wid & 1;
    int lq = lane >> 2, lr = lane & 3;

    for (int i = tid; i < 2 * COUT; i += 256) s_st[i] = 0.f;

    float acc[2][NT][4];
#pragma unroll
    for (int t = 0; t < 2; t++)
#pragma unroll
        for (int n = 0; n < NT; n++) {
            float b0 = bias[n * 8 + 2 * lr], b1v = bias[n * 8 + 2 * lr + 1];
            acc[t][n][0] = b0; acc[t][n][1] = b1v; acc[t][n][2] = b0; acc[t][n][3] = b1v;
        }

    const uint4* actu4 = (const uint4*)act;
    const uint4* wxu4  = (const uint4*)wext;

    for (int s = 0; s < SLABS; s++) {
        int g = s / 25, tap = s % 25;
        int dt = tap / 5, dz = tap % 5;
        int d1s = d1 + dt - 2, d2s = d2 + dz - 2;
        bool v12 = ((unsigned)d1s < 8u) && ((unsigned)d2s < 16u);
        int pbase = g * NV;
        int vb = ((b * 8 + d1s) * 16 + d2s) * 1024;
        __syncthreads();
        // stage A: 12 srows x 36 d4p, 2 uint4 each
        for (int i = tid; i < 864; i += 256) {
            int q = i & 1, cell = i >> 1;
            int d4p = cell % 36, srow = cell / 36;
            int d3s = d3b + srow - 2;
            uint4 v = make_uint4(0, 0, 0, 0);
            if (v12 && (unsigned)d3s < 32u && d4p >= 2 && d4p < 34)
                v = actu4[((long)(pbase + vb + d3s * 32 + d4p - 2) << 1) + q];
            *(uint4*)(sA + cell * 12 + q * 4) = v;
        }
        // stage W slab
        {
            const uint4* wsrc = wxu4 + (long)s * (SW_U32 / 4);
            for (int i = tid; i < SW_U32 / 4; i += 256) ((uint4*)sW)[i] = wsrc[i];
        }
        __syncthreads();

#pragma unroll 1
        for (int dy = 0; dy < 5; dy++) {
            int ar0 = ((d3r0 + dy) * 36 + h * 16 + lq) * 12 + lr;   // m-tile0, row lq
            int ar1 = ar0 + 96;                                      // row lq+8 (+8 d4)
            int br0 = ar0 + 1728;                                    // m-tile1 (+4 d3rows)
            int br1 = br0 + 96;
            int wb = (dy * COUT + lq) * 44 + lr;
#pragma unroll
            for (int kc = 0; kc < 5; kc++) {
                int ko = kc * 12;
                unsigned a00 = sA[ar0 + ko], a01 = sA[ar1 + ko];
                unsigned a02 = sA[ar0 + ko + 4], a03 = sA[ar1 + ko + 4];
                unsigned a10 = sA[br0 + ko], a11 = sA[br1 + ko];
                unsigned a12 = sA[br0 + ko + 4], a13 = sA[br1 + ko + 4];
#pragma unroll
                for (int n = 0; n < NT; n++) {
                    unsigned b0 = sW[wb + n * 352 + kc * 8];
                    unsigned b1 = sW[wb + n * 352 + kc * 8 + 4];
                    mma_f16(acc[0][n], a00, a01, a02, a03, b0, b1);
                    mma_f16(acc[1][n], a10, a11, a12, a13, b0, b1);
                }
            }
        }
    }

    // epilogue: store fp32 + fused BN stats
    int vox0 = ((b * 8 + d1) * 16 + d2) * 1024 + d3b * 32;
#pragma unroll
    for (int t = 0; t < 2; t++) {
        int d3r = d3r0 + 4 * t;
        long base = (long)(vox0 + d3r * 32 + h * 16 + lq) * COUT + 2 * lr;
#pragma unroll
        for (int n = 0; n < NT; n++) {
            *(float2*)&fout[base + n * 8]            = make_float2(acc[t][n][0], acc[t][n][1]);
            *(float2*)&fout[base + 8 * COUT + n * 8] = make_float2(acc[t][n][2], acc[t][n][3]);
        }
    }
    // stats: reduce over lq lanes (stride-4 groups), then smem atomics
#pragma unroll
    for (int n = 0; n < NT; n++) {
        float s0 = 0.f, s1 = 0.f, q0 = 0.f, q1 = 0.f;
#pragma unroll
        for (int t = 0; t < 2; t++) {
            s0 += acc[t][n][0] + acc[t][n][2];
            s1 += acc[t][n][1] + acc[t][n][3];
            q0 += acc[t][n][0] * acc[t][n][0] + acc[t][n][2] * acc[t][n][2];
            q1 += acc[t][n][1] * acc[t][n][1] + acc[t][n][3] * acc[t][n][3];
        }
#pragma unroll
        for (int off = 16; off >= 4; off >>= 1) {
            s0 += __shfl_down_sync(0xffffffffu, s0, off);
            s1 += __shfl_down_sync(0xffffffffu, s1, off);
            q0 += __shfl_down_sync(0xffffffffu, q0, off);
            q1 += __shfl_down_sync(0xffffffffu, q1, off);
        }
        if (lq == 0) {
            int ch = n * 8 + 2 * lr;
            atomicAdd(&s_st[ch], s0);
            atomicAdd(&s_st[ch + 1], s1);
            atomicAdd(&s_st[COUT + ch], q0);
            atomicAdd(&s_st[COUT + ch + 1], q1);
        }
    }
    __syncthreads();
    if (tid < COUT)       atomicAdd(&gsum[tid], (double)s_st[tid]);
    else if (tid < 2 * COUT) atomicAdd(&gssq[tid - COUT], (double)s_st[tid]);
}

// ---------------- bn apply (+ leaky relu) -> fp16 planes ----------------
template <int C>
__global__ void bn_apply_kernel(const float* __restrict__ fout, const double* __restrict__ sum,
                                const double* __restrict__ ssq, const float* __restrict__ gamma,
                                const float* __restrict__ beta, unsigned* __restrict__ act) {
    constexpr int NPL = C / 16;
    __shared__ float sc[C], sh[C];
    int tid = threadIdx.x;
    if (tid < C) {
        double m   = sum[tid] / (double)NV;
        double var = ssq[tid] / (double)NV - m * m;
        double inv = 1.0 / sqrt(var + 1e-5);
        float s = gamma[tid] * (float)inv;
        sc[tid] = s;
        sh[tid] = beta[tid] - (float)m * s;
    }
    __syncthreads();
    long total  = (long)NV * NPL;
    long stride = (long)gridDim.x * blockDim.x;
    for (long id = blockIdx.x * (long)blockDim.x + tid; id < total; id += stride) {
        int vox = (int)(id % NV);
        int pl  = (int)(id / NV);
        const float4* src = (const float4*)&fout[(long)vox * C + pl * 16];
        float4 v0 = src[0], v1 = src[1], v2 = src[2], v3 = src[3];
        float vv[16] = {v0.x, v0.y, v0.z, v0.w, v1.x, v1.y, v1.z, v1.w,
                        v2.x, v2.y, v2.z, v2.w, v3.x, v3.y, v3.z, v3.w};
        unsigned p[8];
#pragma unroll
        for (int q = 0; q < 8; q++) {
            float r0 = vv[2*q]   * sc[pl*16 + 2*q]   + sh[pl*16 + 2*q];
            float r1 = vv[2*q+1] * sc[pl*16 + 2*q+1] + sh[pl*16 + 2*q+1];
            r0 = fmaxf(r0, LRELU * r0);
            r1 = fmaxf(r1, LRELU * r1);
            p[q] = packh2(r0, r1);
        }
        uint4* dst = (uint4*)&act[((long)pl * NV + vox) * 8];
        dst[0] = make_uint4(p[0], p[1], p[2], p[3]);
        dst[1] = make_uint4(p[4], p[5], p[6], p[7]);
    }
}

// ---------------- fused BN + leaky relu + projection (layer 3) ----------------
__global__ void bnproj_kernel(const float* __restrict__ fout, const double* __restrict__ sum,
                              const double* __restrict__ ssq, const float* __restrict__ gamma,
                              const float* __restrict__ beta, const float* __restrict__ wp,
                              const float* __restrict__ bp, float* __restrict__ out) {
    __shared__ float sc[H], sh[H], sw[H];
    __shared__ float sb;
    int tid = threadIdx.x;
    if (tid < H) {
        double m   = sum[tid] / (double)NV;
        double var = ssq[tid] / (double)NV - m * m;
        double inv = 1.0 / sqrt(var + 1e-5);
        float s = gamma[tid] * (float)inv;
        sc[tid] = s;
        sh[tid] = beta[tid] - (float)m * s;
        sw[tid] = wp[tid];
    }
    if (tid == 0) sb = bp[0];
    __syncthreads();
    int v = blockIdx.x * blockDim.x + tid;
    if (v >= NV) return;
    const float4* src = (const float4*)&fout[(long)v * H];
    float4 v0 = src[0], v1 = src[1], v2 = src[2], v3 = src[3];
    float vv[16] = {v0.x, v0.y, v0.z, v0.w, v1.x, v1.y, v1.z, v1.w,
                    v2.x, v2.y, v2.z, v2.w, v3.x, v3.y, v3.z, v3.w};
    float a = sb;
#pragma unroll
    for (int c = 0; c < H; c++) {
        float r = vv[c] * sc[c] + sh[c];
        r = fmaxf(r, LRELU * r);
        a += r * sw[c];
    }
    out[v] = a;
}

// ---------------- launch ----------------
extern "C" void kernel_launch(void* const* d_in, const int* in_sizes, int n_in,
                              void* d_out, int out_size) {
    const float* x      = (const float*)d_in[0];
    const float* w_emb  = (const float*)d_in[1];
    const float* b_emb  = (const float*)d_in[2];
    const float* W1     = (const float*)d_in[3];
    const float* b1     = (const float*)d_in[4];
    const float* g1     = (const float*)d_in[5];
    const float* be1    = (const float*)d_in[6];
    const float* W2     = (const float*)d_in[7];
    const float* b2     = (const float*)d_in[8];
    const float* g2     = (const float*)d_in[9];
    const float* be2    = (const float*)d_in[10];
    const float* W3     = (const float*)d_in[11];
    const float* b3     = (const float*)d_in[12];
    const float* g3     = (const float*)d_in[13];
    const float* be3    = (const float*)d_in[14];
    const float* w_proj = (const float*)d_in[15];
    const float* b_proj = (const float*)d_in[16];

    unsigned *actA, *actB, *actC, *wx1, *wx2, *wx3;
    float* fout;
    double *sums, *ssqs;
    cudaGetSymbolAddress((void**)&actA, g_actA);
    cudaGetSymbolAddress((void**)&actB, g_actB);
    cudaGetSymbolAddress((void**)&actC, g_actC);
    cudaGetSymbolAddress((void**)&fout, g_fout);
    cudaGetSymbolAddress((void**)&wx1, g_wx1);
    cudaGetSymbolAddress((void**)&wx2, g_wx2);
    cudaGetSymbolAddress((void**)&wx3, g_wx3);
    cudaGetSymbolAddress((void**)&sums, g_sum);
    cudaGetSymbolAddress((void**)&ssqs, g_ssq);

    // smem: A 20736 + W (5*COUT*44*4) + stats (2*COUT*4)
    // conv1/3: 20736 + 14080 + 128 = 34944 ; conv2: 20736 + 28160 + 256 = 49152
    cudaFuncSetAttribute(conv_mma_kernel<16, 25>, cudaFuncAttributeMaxDynamicSharedMemorySize, 34944);
    cudaFuncSetAttribute(conv_mma_kernel<32, 25>, cudaFuncAttributeMaxDynamicSharedMemorySize, 49152);
    cudaFuncSetAttribute(conv_mma_kernel<16, 50>, cudaFuncAttributeMaxDynamicSharedMemorySize, 34944);

    zero_stats_kernel<<<1, 128>>>(sums, ssqs);
    wext_kernel<<<(88000 + 255) / 256, 256>>>(W1, wx1, 16, 16, 88000);
    wext_kernel<<<(176000 + 255) / 256, 256>>>(W2, wx2, 32, 16, 176000);
    wext_kernel<<<(176000 + 255) / 256, 256>>>(W3, wx3, 16, 32, 176000);

    embed_kernel<<<NV / 256, 256>>>(x, w_emb, b_emb, actA);

    conv_mma_kernel<16, 25><<<1024, 256, 34944>>>(actA, wx1, b1, fout, sums + 0, ssqs + 0);
    bn_apply_kernel<16><<<1024, 256>>>(fout, sums + 0, ssqs + 0, g1, be1, actB);

    conv_mma_kernel<32, 25><<<1024, 256, 49152>>>(actB, wx2, b2, fout, sums + 32, ssqs + 32);
    bn_apply_kernel<32><<<2048, 256>>>(fout, sums + 32, ssqs + 32, g2, be2, actC);

    conv_mma_kernel<16, 50><<<1024, 256, 34944>>>(actC, wx3, b3, fout, sums + 64, ssqs + 64);
    bnproj_kernel<<<NV / 256, 256>>>(fout, sums + 64, ssqs + 64, g3, be3, w_proj, b_proj, (float*)d_out);
}